// round 9
// baseline (speedup 1.0000x reference)
#include <cuda_runtime.h>
#include <math.h>
#include <stdint.h>

#define BSZ 2
#define SEQ 2048
#define HIDDEN 2048
#define NH 32
#define NKV 8
#define HD 64
#define NREP 4

// Scratch (static device arrays — no allocation).
__device__ float g_q[BSZ * NH * SEQ * HD];      // [b, h, s, d] tf32-rounded, pre-scaled 1/8
__device__ float g_k[BSZ * NKV * SEQ * HD];     // [b, kvh, s, d] tf32-rounded
__device__ float g_v[BSZ * NKV * SEQ * HD];     // [b, kvh, s, d] tf32-rounded
__device__ float g_attn[BSZ * SEQ * NH * HD];   // [b, s, h*d] tf32-rounded

__device__ float g_ht[BSZ * SEQ * HIDDEN];      // tf32-rounded hidden
__device__ float g_wqt[NH * HD * HIDDEN];       // [N,K] k-major, tf32-rounded
__device__ float g_wkt[NKV * HD * HIDDEN];
__device__ float g_wvt[NKV * HD * HIDDEN];
__device__ float g_wot[HIDDEN * NH * HD];       // [N=2048, K=2048]

// ---------------------------------------------------------------------------
// Helpers
// ---------------------------------------------------------------------------
__device__ __forceinline__ float tf32r(float x) {
    unsigned u;
    asm("cvt.rna.tf32.f32 %0, %1;" : "=r"(u) : "f"(x));
    return __uint_as_float(u);
}
#define F2U __float_as_uint

__device__ __forceinline__ void mma8(float c[4],
                                     unsigned a0, unsigned a1, unsigned a2, unsigned a3,
                                     unsigned b0, unsigned b1) {
    asm volatile(
        "mma.sync.aligned.m16n8k8.row.col.f32.tf32.tf32.f32 "
        "{%0,%1,%2,%3}, {%4,%5,%6,%7}, {%8,%9}, {%0,%1,%2,%3};\n"
        : "+f"(c[0]), "+f"(c[1]), "+f"(c[2]), "+f"(c[3])
        : "r"(a0), "r"(a1), "r"(a2), "r"(a3), "r"(b0), "r"(b1));
}
__device__ __forceinline__ void ldsm4(unsigned& r0, unsigned& r1,
                                      unsigned& r2, unsigned& r3, uint32_t addr) {
    asm volatile("ldmatrix.sync.aligned.m8n8.x4.shared.b16 {%0,%1,%2,%3}, [%4];"
                 : "=r"(r0), "=r"(r1), "=r"(r2), "=r"(r3) : "r"(addr));
}

// ---------------------------------------------------------------------------
// Prologue kernels: elementwise round; tiled transpose+round
// ---------------------------------------------------------------------------
__global__ void round_tf32(const float* __restrict__ src, float* __restrict__ dst, int n4)
{
    int i = blockIdx.x * blockDim.x + threadIdx.x;
    if (i >= n4) return;
    float4 v = ((const float4*)src)[i];
    v.x = tf32r(v.x); v.y = tf32r(v.y); v.z = tf32r(v.z); v.w = tf32r(v.w);
    ((float4*)dst)[i] = v;
}

// dst[n*Kd + k] = tf32r(src[k*Nd + n])
__global__ void transpose_tf32(const float* __restrict__ src, float* __restrict__ dst,
                               int Kd, int Nd)
{
    __shared__ float t[32][33];
    const int n0 = blockIdx.x * 32, k0 = blockIdx.y * 32;
    const int tx = threadIdx.x, ty = threadIdx.y;
#pragma unroll
    for (int i = 0; i < 4; i++)
        t[ty + i * 8][tx] = src[(size_t)(k0 + ty + i * 8) * Nd + n0 + tx];
    __syncthreads();
#pragma unroll
    for (int i = 0; i < 4; i++)
        dst[(size_t)(n0 + ty + i * 8) * Kd + k0 + tx] = tf32r(t[tx][ty + i * 8]);
}

// ---------------------------------------------------------------------------
// GEMM mainloop v3 (unchanged from R8): 128x128 tile, BK=32, 3-stage cp.async,
// XOR-swizzled smem. Both fragments via ldmatrix.
// ---------------------------------------------------------------------------
#define STAGE_B 16384u
#define GEMM_SMEM (6 * 16384)

template<int WARPS_M>
__device__ __forceinline__ void gemm_mainloop3(
    const float* __restrict__ Ag, const float* __restrict__ Bg,
    int K, float (*acc)[4])
{
    extern __shared__ float smem[];
    constexpr int MT = 8 / WARPS_M;
    constexpr int NT = 2 * WARPS_M;
    constexpr int NPAIR = NT / 2;

    const int tid  = threadIdx.x;
    const int lane = tid & 31;
    const int warp = tid >> 5;
    const int wm   = warp % WARPS_M;
    const int wn   = warp / WARPS_M;

    const uint32_t sA = (uint32_t)__cvta_generic_to_shared(smem);
    const uint32_t sB = sA + 3 * STAGE_B;

    const int lrow = tid >> 3;
    const int lj   = tid & 7;
    const uint32_t wsw = (uint32_t)((lj ^ (lrow & 7)) << 4);

    const int frow = ((lane >> 3) & 1) * 8 + (lane & 7);
    const int fjb  = lane >> 4;
    const int axr  = frow & 7;
    const uint32_t arowb = (uint32_t)((wm * MT * 16 + frow) * 128);
    const int brow = (lane & 7) + ((lane >> 4) & 1) * 8;
    const int bjb  = (lane >> 3) & 1;
    const int bxr  = brow & 7;
    const uint32_t browb = (uint32_t)((wn * NT * 8 + brow) * 128);

#define ISSUE(kc, st) do {                                                           \
    _Pragma("unroll")                                                                \
    for (int i = 0; i < 4; i++) {                                                    \
        const int r = lrow + 32 * i;                                                 \
        const float* sa = Ag + (size_t)r * K + (kc) * 32 + lj * 4;                   \
        const uint32_t da = sA + (uint32_t)(st) * STAGE_B + (uint32_t)(r * 128) + wsw; \
        asm volatile("cp.async.cg.shared.global [%0], [%1], 16;" :: "r"(da), "l"(sa)); \
    }                                                                                \
    _Pragma("unroll")                                                                \
    for (int i = 0; i < 4; i++) {                                                    \
        const int r = lrow + 32 * i;                                                 \
        const float* sb = Bg + (size_t)r * K + (kc) * 32 + lj * 4;                   \
        const uint32_t db = sB + (uint32_t)(st) * STAGE_B + (uint32_t)(r * 128) + wsw; \
        asm volatile("cp.async.cg.shared.global [%0], [%1], 16;" :: "r"(db), "l"(sb)); \
    }                                                                                \
    asm volatile("cp.async.commit_group;");                                          \
} while (0)

    const int nkc = K >> 5;
    ISSUE(0, 0);
    ISSUE(1, 1);

    for (int kc = 0; kc < nkc; kc++) {
        if (kc < nkc - 1) asm volatile("cp.async.wait_group 1;");
        else              asm volatile("cp.async.wait_group 0;");
        __syncthreads();

        const int st = kc % 3;
        const uint32_t aS = sA + (uint32_t)st * STAGE_B;
        const uint32_t bS = sB + (uint32_t)st * STAGE_B;

#pragma unroll
        for (int ks = 0; ks < 4; ks++) {
            unsigned a[MT][4];
#pragma unroll
            for (int mt = 0; mt < MT; mt++)
                ldsm4(a[mt][0], a[mt][1], a[mt][2], a[mt][3],
                      aS + arowb + (uint32_t)(mt * 2048)
                         + (uint32_t)((((2 * ks + fjb) ^ axr)) << 4));
#pragma unroll
            for (int ntp = 0; ntp < NPAIR; ntp++) {
                unsigned b0, b1, b2, b3;
                ldsm4(b0, b1, b2, b3,
                      bS + browb + (uint32_t)(ntp * 2048)
                         + (uint32_t)((((2 * ks + bjb) ^ bxr)) << 4));
#pragma unroll
                for (int mt = 0; mt < MT; mt++) {
                    mma8(acc[mt * NT + 2 * ntp],     a[mt][0], a[mt][1], a[mt][2], a[mt][3], b0, b1);
                    mma8(acc[mt * NT + 2 * ntp + 1], a[mt][0], a[mt][1], a[mt][2], a[mt][3], b2, b3);
                }
            }
        }
        if (kc + 2 < nkc) ISSUE(kc + 2, (kc + 2) % 3);
    }
#undef ISSUE
}

// ---------------------------------------------------------------------------
// Fused QKV projection + RoPE epilogue (unchanged from R8).
// ---------------------------------------------------------------------------
__global__ __launch_bounds__(256, 2)
void qkv_gemm()
{
    const int bx = blockIdx.x, by = blockIdx.y;
    const int tid = threadIdx.x;
    const int lane = tid & 31, warp = tid >> 5;
    const int wm = warp % 4, wn = warp / 4;
    const int q = lane & 3, g = lane >> 2;

    const float* W;
    float* Out;
    int cb, heads;
    bool rope;
    float oscale;
    if (bx < 16)      { W = g_wqt; Out = g_q; cb = bx * 128;        heads = NH;  rope = true;  oscale = 0.125f; }
    else if (bx < 20) { W = g_wkt; Out = g_k; cb = (bx - 16) * 128; heads = NKV; rope = true;  oscale = 1.0f; }
    else              { W = g_wvt; Out = g_v; cb = (bx - 20) * 128; heads = NKV; rope = false; oscale = 1.0f; }

    float acc[16][4];
#pragma unroll
    for (int i = 0; i < 16; i++)
#pragma unroll
        for (int j = 0; j < 4; j++) acc[i][j] = 0.0f;

    gemm_mainloop3<4>(g_ht + (size_t)(by * 128) * HIDDEN,
                      W + (size_t)cb * HIDDEN, HIDDEN, acc);

    if (rope) {
        float invf[8];
#pragma unroll
        for (int ntp = 0; ntp < 4; ntp++)
#pragma unroll
            for (int j = 0; j < 2; j++)
                invf[ntp * 2 + j] =
                    powf(10000.0f, -((float)(2 * (ntp * 8 + (q << 1) + j)) / 64.0f));
#pragma unroll
        for (int mt = 0; mt < 2; mt++) {
#pragma unroll
            for (int rh = 0; rh < 2; rh++) {
                const int m = by * 128 + wm * 32 + mt * 16 + g + rh * 8;
                const float s = (float)(m & (SEQ - 1));
#pragma unroll
                for (int ntp = 0; ntp < 4; ntp++) {
#pragma unroll
                    for (int j = 0; j < 2; j++) {
                        float c, si;
                        sincosf(s * invf[ntp * 2 + j], &si, &c);
                        const float x1 = acc[mt * 8 + ntp][rh * 2 + j];
                        const float x2 = acc[mt * 8 + ntp + 4][rh * 2 + j];
                        acc[mt * 8 + ntp][rh * 2 + j]     = x1 * c - x2 * si;
                        acc[mt * 8 + ntp + 4][rh * 2 + j] = x2 * c + x1 * si;
                    }
                }
            }
        }
    }

#pragma unroll
    for (int mt = 0; mt < 2; mt++) {
        const int row = by * 128 + wm * 32 + mt * 16 + g;
#pragma unroll
        for (int nt = 0; nt < 8; nt++) {
            const int col = cb + wn * 64 + nt * 8 + (q << 1);
            const int hh = col / HD, dd = col & (HD - 1);
#pragma unroll
            for (int rh = 0; rh < 2; rh++) {
                const int m = row + rh * 8;
                const int bb = m >> 11, ss = m & (SEQ - 1);
                float* p = Out + (((size_t)bb * heads + hh) * SEQ + ss) * HD + dd;
                p[0] = tf32r(acc[mt * 8 + nt][rh * 2]     * oscale);
                p[1] = tf32r(acc[mt * 8 + nt][rh * 2 + 1] * oscale);
            }
        }
    }
}

// ---------------------------------------------------------------------------
// Output projection (unchanged from R8)
// ---------------------------------------------------------------------------
__global__ __launch_bounds__(256, 2)
void gemm_o(float* __restrict__ C)
{
    const int bx = blockIdx.x, by = blockIdx.y;
    const int tid = threadIdx.x;
    const int lane = tid & 31, warp = tid >> 5;
    const int wm = warp % 2, wn = warp / 2;
    const int q = lane & 3, g = lane >> 2;

    float acc[16][4];
#pragma unroll
    for (int i = 0; i < 16; i++)
#pragma unroll
        for (int j = 0; j < 4; j++) acc[i][j] = 0.0f;

    gemm_mainloop3<2>(g_attn + (size_t)(by * 128) * HIDDEN,
                      g_wot + (size_t)(bx * 128) * HIDDEN, HIDDEN, acc);

#pragma unroll
    for (int mt = 0; mt < 4; mt++) {
        const int row = by * 128 + wm * 64 + mt * 16 + g;
#pragma unroll
        for (int nt = 0; nt < 4; nt++) {
            const int col = bx * 128 + wn * 32 + nt * 8 + (q << 1);
            *(float2*)(C + (size_t)row * HIDDEN + col) =
                make_float2(acc[mt * 4 + nt][0], acc[mt * 4 + nt][1]);
            *(float2*)(C + (size_t)(row + 8) * HIDDEN + col) =
                make_float2(acc[mt * 4 + nt][2], acc[mt * 4 + nt][3]);
        }
    }
}

// ---------------------------------------------------------------------------
// Flash attention v2: 128-row Q tiles, 8 warps (256 thr), double-buffered
// K and V (2 stages each), 2 barriers/tile, causal, tf32 mma.sync.
// Commit order: K0,V0,K1 | per tile kt: V(kt+1) after K-wait barrier,
//               K(kt+2) after V-wait barrier. In-order completion gives
// waitK: N=2 (last tile: 1); waitV: N=2 (last tile: 0).
// Ps (128x68) doubles as Q staging. Heaviest blocks launch first.
// ---------------------------------------------------------------------------
#define QSTR 68
#define VSTR 72
#define KSTG (64 * QSTR)
#define VSTG (64 * VSTR)
#define FLASH_SMEM ((128 * QSTR + 2 * KSTG + 2 * VSTG) * 4)   // 106496 B

__global__ __launch_bounds__(256, 2)
void flash_tf32(const float* __restrict__ Q, const float* __restrict__ K,
                const float* __restrict__ V, float* __restrict__ O)
{
    extern __shared__ float sm[];
    float* Ps = sm;                        // [128][68], Q staging then P
    float* Ks = sm + 128 * QSTR;           // 2 x [64][68]
    float* Vs = Ks + 2 * KSTG;             // 2 x [64][72]

    const int qb   = gridDim.x - 1 - blockIdx.x;   // heavy blocks first
    const int h    = blockIdx.y;
    const int b    = blockIdx.z;
    const int tid  = threadIdx.x;
    const int lane = tid & 31;
    const int warp = tid >> 5;
    const int q    = lane & 3;
    const int g    = lane >> 2;

    const float* Qg = Q + (((size_t)b * NH + h) * SEQ + qb * 128) * HD;
    const float* Kg = K + ((size_t)b * NKV + h / NREP) * SEQ * HD;
    const float* Vg = V + ((size_t)b * NKV + h / NREP) * SEQ * HD;

    const uint32_t sKs = (uint32_t)__cvta_generic_to_shared(Ks);
    const uint32_t sVs = (uint32_t)__cvta_generic_to_shared(Vs);
    const uint32_t sPs = (uint32_t)__cvta_generic_to_shared(Ps);

    // 64x64 tile = 1024 float4; 256 thr -> 4 each
    auto issue_k = [&](int kt) {
        const uint32_t stb = (uint32_t)((kt & 1) * KSTG * 4);
#pragma unroll
        for (int i = 0; i < 4; i++) {
            const int f = tid + 256 * i;
            const int r = f >> 4, c4 = (f & 15) << 2;
            const uint32_t d = sKs + stb + (uint32_t)((r * QSTR + c4) * 4);
            const float* s = Kg + (size_t)kt * 64 * HD + f * 4;
            asm volatile("cp.async.cg.shared.global [%0], [%1], 16;" :: "r"(d), "l"(s));
        }
        asm volatile("cp.async.commit_group;");
    };
    auto issue_v = [&](int kt) {
        const uint32_t stb = (uint32_t)((kt & 1) * VSTG * 4);
#pragma unroll
        for (int i = 0; i < 4; i++) {
            const int f = tid + 256 * i;
            const int r = f >> 4, c4 = (f & 15) << 2;
            const uint32_t d = sVs + stb + (uint32_t)((r * VSTR + c4) * 4);
            const float* s = Vg + (size_t)kt * 64 * HD + f * 4;
            asm volatile("cp.async.cg.shared.global [%0], [%1], 16;" :: "r"(d), "l"(s));
        }
        asm volatile("cp.async.commit_group;");
    };

    const int nkt = 2 * qb + 2;

    // Prologue: K0, V0, K1 in flight (nkt >= 2 always)
    issue_k(0);
    issue_v(0);
    issue_k(1);

    // Stage Q into Ps: 128x64 = 2048 float4, 8 per thread
#pragma unroll
    for (int i = 0; i < 8; i++) {
        const int f = tid + 256 * i;
        const int r = f >> 4, c4 = (f & 15) << 2;
        *(float4*)&Ps[r * QSTR + c4] = *(const float4*)&Qg[r * HD + c4];
    }
    __syncthreads();

    const int rA = warp * 16 + g;       // 0..127

    // Hoist Q fragments (warp-private rows; Ps then becomes P)
    unsigned qf[8][4];
#pragma unroll
    for (int ks = 0; ks < 8; ks++) {
        const int k0 = ks * 8;
        qf[ks][0] = F2U(Ps[rA * QSTR + k0 + q]);
        qf[ks][1] = F2U(Ps[(rA + 8) * QSTR + k0 + q]);
        qf[ks][2] = F2U(Ps[rA * QSTR + k0 + 4 + q]);
        qf[ks][3] = F2U(Ps[(rA + 8) * QSTR + k0 + 4 + q]);
    }

    // ldmatrix bases
    const int arow = ((lane >> 3) & 1) * 8 + (lane & 7);
    const int acol = (lane >> 4) * 4;
    const uint32_t pbase = sPs + (uint32_t)(((warp * 16 + arow) * QSTR + acol) * 4);
    const int krow = (lane & 7) + ((lane >> 4) & 1) * 8;
    const int kcol = ((lane >> 3) & 1) * 4;
    const uint32_t kf4 = sKs + (uint32_t)((krow * QSTR + kcol) * 4);

    float m_i[2], l_i[2], o_acc[8][4];
#pragma unroll
    for (int rh = 0; rh < 2; rh++) { m_i[rh] = -INFINITY; l_i[rh] = 0.0f; }
#pragma unroll
    for (int nt = 0; nt < 8; nt++)
#pragma unroll
        for (int j = 0; j < 4; j++) o_acc[nt][j] = 0.0f;

    for (int kt = 0; kt < nkt; kt++) {
        const uint32_t kstb = (uint32_t)((kt & 1) * KSTG * 4);
        const uint32_t vst0 = (uint32_t)((kt & 1) * VSTG);

        // K(kt) ready
        if (kt < nkt - 1) asm volatile("cp.async.wait_group 2;");
        else              asm volatile("cp.async.wait_group 1;");
        __syncthreads();                       // barrier A (also: PV(kt-1) done)
        if (kt + 1 < nkt) issue_v(kt + 1);     // Vs[(kt+1)&1] free since PV(kt-1) done

        // S = Q @ K^T
        float s_acc[8][4];
#pragma unroll
        for (int nt = 0; nt < 8; nt++)
#pragma unroll
            for (int j = 0; j < 4; j++) s_acc[nt][j] = 0.0f;

#pragma unroll
        for (int ks = 0; ks < 8; ks++) {
#pragma unroll
            for (int ntp = 0; ntp < 4; ntp++) {
                unsigned b0, b1, b2, b3;
                ldsm4(b0, b1, b2, b3,
                      kf4 + kstb + (uint32_t)((ntp * 16 * QSTR + ks * 8) * 4));
                mma8(s_acc[2 * ntp],     qf[ks][0], qf[ks][1], qf[ks][2], qf[ks][3], b0, b1);
                mma8(s_acc[2 * ntp + 1], qf[ks][0], qf[ks][1], qf[ks][2], qf[ks][3], b2, b3);
            }
        }

        const bool diag = (kt >= 2 * qb);

        // Online softmax per row-half (Q pre-scaled by 1/8)
#pragma unroll
        for (int rh = 0; rh < 2; rh++) {
            const int rg = qb * 128 + rA + rh * 8;
            float mx = -INFINITY;
#pragma unroll
            for (int nt = 0; nt < 8; nt++) {
#pragma unroll
                for (int j = 0; j < 2; j++) {
                    float sv = s_acc[nt][rh * 2 + j];
                    if (diag) {
                        int cg = kt * 64 + nt * 8 + (q << 1) + j;
                        if (cg > rg) sv = -INFINITY;
                    }
                    s_acc[nt][rh * 2 + j] = sv;
                    mx = fmaxf(mx, sv);
                }
            }
            mx = fmaxf(mx, __shfl_xor_sync(0xffffffffu, mx, 1));
            mx = fmaxf(mx, __shfl_xor_sync(0xffffffffu, mx, 2));

            const float mnew = fmaxf(m_i[rh], mx);
            const float sc = __expf(m_i[rh] - mnew);
            m_i[rh] = mnew;

            float rs = 0.0f;
#pragma unroll
            for (int nt = 0; nt < 8; nt++) {
#pragma unroll
                for (int j = 0; j < 2; j++) {
                    float p = __expf(s_acc[nt][rh * 2 + j] - mnew);
                    s_acc[nt][rh * 2 + j] = p;
                    rs += p;
                }
            }
            rs += __shfl_xor_sync(0xffffffffu, rs, 1);
            rs += __shfl_xor_sync(0xffffffffu, rs, 2);

            l_i[rh] = l_i[rh] * sc + rs;
#pragma unroll
            for (int nt = 0; nt < 8; nt++) {
                o_acc[nt][rh * 2]     *= sc;
                o_acc[nt][rh * 2 + 1] *= sc;
            }
        }

        // Stage P (warp-private rows)
#pragma unroll
        for (int nt = 0; nt < 8; nt++) {
            const int c = nt * 8 + (q << 1);
            Ps[rA * QSTR + c]           = tf32r(s_acc[nt][0]);
            Ps[rA * QSTR + c + 1]       = tf32r(s_acc[nt][1]);
            Ps[(rA + 8) * QSTR + c]     = tf32r(s_acc[nt][2]);
            Ps[(rA + 8) * QSTR + c + 1] = tf32r(s_acc[nt][3]);
        }
        __syncwarp();

        // V(kt) ready
        if (kt < nkt - 1) asm volatile("cp.async.wait_group 2;");
        else              asm volatile("cp.async.wait_group 0;");
        __syncthreads();                       // barrier B (also: S reads of Ks done)
        if (kt + 2 < nkt) issue_k(kt + 2);     // Ks[kt&1] free since S(kt) done

        // O += P @ V
#pragma unroll
        for (int ks = 0; ks < 8; ks++) {
            const int k0 = ks * 8;
            unsigned a0, a1, a2, a3;
            ldsm4(a0, a1, a2, a3, pbase + (uint32_t)(k0 * 4));
#pragma unroll
            for (int nt = 0; nt < 8; nt++) {
                const int n = nt * 8 + g;
                const unsigned b0 = F2U(Vs[vst0 + (k0 + q) * VSTR + n]);
                const unsigned b1 = F2U(Vs[vst0 + (k0 + 4 + q) * VSTR + n]);
                mma8(o_acc[nt], a0, a1, a2, a3, b0, b1);
            }
        }
    }

    // Normalize, tf32-round (feeds gemm_o), write [b, s, h*HD]
    const float inv0 = 1.0f / l_i[0];
    const float inv1 = 1.0f / l_i[1];
#pragma unroll
    for (int nt = 0; nt < 8; nt++) {
        const int c = nt * 8 + (q << 1);
        const int r0 = qb * 128 + rA;
        float* p0 = O + ((size_t)b * SEQ + r0) * (NH * HD) + h * HD + c;
        p0[0] = tf32r(o_acc[nt][0] * inv0);
        p0[1] = tf32r(o_acc[nt][1] * inv0);
        float* p1 = O + ((size_t)b * SEQ + r0 + 8) * (NH * HD) + h * HD + c;
        p1[0] = tf32r(o_acc[nt][2] * inv1);
        p1[1] = tf32r(o_acc[nt][3] * inv1);
    }
}

// ---------------------------------------------------------------------------
// kernel_launch
// ---------------------------------------------------------------------------
extern "C" void kernel_launch(void* const* d_in, const int* in_sizes, int n_in,
                              void* d_out, int out_size)
{
    const float* hidden = (const float*)d_in[0];
    const float* wq = (const float*)d_in[1];
    const float* wk = (const float*)d_in[2];
    const float* wv = (const float*)d_in[3];
    const float* wo = (const float*)d_in[4];
    float* out = (float*)d_out;

    float *pq, *pk, *pv, *pattn, *pht, *pwqt, *pwkt, *pwvt, *pwot;
    cudaGetSymbolAddress((void**)&pq, g_q);
    cudaGetSymbolAddress((void**)&pk, g_k);
    cudaGetSymbolAddress((void**)&pv, g_v);
    cudaGetSymbolAddress((void**)&pattn, g_attn);
    cudaGetSymbolAddress((void**)&pht, g_ht);
    cudaGetSymbolAddress((void**)&pwqt, g_wqt);
    cudaGetSymbolAddress((void**)&pwkt, g_wkt);
    cudaGetSymbolAddress((void**)&pwvt, g_wvt);
    cudaGetSymbolAddress((void**)&pwot, g_wot);

    const int M = BSZ * SEQ;   // 4096

    cudaFuncSetAttribute(qkv_gemm, cudaFuncAttributeMaxDynamicSharedMemorySize, GEMM_SMEM);
    cudaFuncSetAttribute(gemm_o, cudaFuncAttributeMaxDynamicSharedMemorySize, GEMM_SMEM);
    cudaFuncSetAttribute(flash_tf32, cudaFuncAttributeMaxDynamicSharedMemorySize, FLASH_SMEM);

    // 1) round hidden; transpose+round weights to [N,K]
    const int nh4 = BSZ * SEQ * HIDDEN / 4;
    round_tf32<<<(nh4 + 255) / 256, 256>>>(hidden, pht, nh4);
    transpose_tf32<<<dim3((NH * HD) / 32, HIDDEN / 32), dim3(32, 8)>>>(wq, pwqt, HIDDEN, NH * HD);
    transpose_tf32<<<dim3((NKV * HD) / 32, HIDDEN / 32), dim3(32, 8)>>>(wk, pwkt, HIDDEN, NKV * HD);
    transpose_tf32<<<dim3((NKV * HD) / 32, HIDDEN / 32), dim3(32, 8)>>>(wv, pwvt, HIDDEN, NKV * HD);
    transpose_tf32<<<dim3(HIDDEN / 32, (NH * HD) / 32), dim3(32, 8)>>>(wo, pwot, NH * HD, HIDDEN);

    // 2) fused QKV projection + RoPE (24 N-tiles: 16 Q, 4 K, 4 V)
    qkv_gemm<<<dim3(24, M / 128), dim3(256), GEMM_SMEM>>>();

    // 3) flash attention (128-row Q tiles, double-buffered K/V)
    flash_tf32<<<dim3(SEQ / 128, NH, BSZ), dim3(256), FLASH_SMEM>>>(pq, pk, pv, pattn);

    // 4) output projection
    gemm_o<<<dim3(HIDDEN / 128, M / 128), dim3(256), GEMM_SMEM>>>(out);
}

// round 10
// speedup vs baseline: 1.6178x; 1.6178x over previous
#include <cuda_runtime.h>
#include <math.h>
#include <stdint.h>

#define BSZ 2
#define SEQ 2048
#define HIDDEN 2048
#define NH 32
#define NKV 8
#define HD 64
#define NREP 4

// Scratch (static device arrays — no allocation).
__device__ float g_q[BSZ * NH * SEQ * HD];      // [b, h, s, d] tf32-rounded, pre-scaled 1/8
__device__ float g_k[BSZ * NKV * SEQ * HD];     // [b, kvh, s, d] tf32-rounded
__device__ float g_v[BSZ * NKV * SEQ * HD];     // [b, kvh, s, d] tf32-rounded
__device__ float g_attn[BSZ * SEQ * NH * HD];   // [b, s, h*d] tf32-rounded

__device__ float g_ht[BSZ * SEQ * HIDDEN];      // tf32-rounded hidden
__device__ float g_wqt[NH * HD * HIDDEN];       // [N,K] k-major, tf32-rounded
__device__ float g_wkt[NKV * HD * HIDDEN];
__device__ float g_wvt[NKV * HD * HIDDEN];
__device__ float g_wot[HIDDEN * NH * HD];       // [N=2048, K=2048]

// ---------------------------------------------------------------------------
// Helpers
// ---------------------------------------------------------------------------
__device__ __forceinline__ float tf32r(float x) {
    unsigned u;
    asm("cvt.rna.tf32.f32 %0, %1;" : "=r"(u) : "f"(x));
    return __uint_as_float(u);
}
#define F2U __float_as_uint

__device__ __forceinline__ void mma8(float c[4],
                                     unsigned a0, unsigned a1, unsigned a2, unsigned a3,
                                     unsigned b0, unsigned b1) {
    asm volatile(
        "mma.sync.aligned.m16n8k8.row.col.f32.tf32.tf32.f32 "
        "{%0,%1,%2,%3}, {%4,%5,%6,%7}, {%8,%9}, {%0,%1,%2,%3};\n"
        : "+f"(c[0]), "+f"(c[1]), "+f"(c[2]), "+f"(c[3])
        : "r"(a0), "r"(a1), "r"(a2), "r"(a3), "r"(b0), "r"(b1));
}
__device__ __forceinline__ void ldsm4(unsigned& r0, unsigned& r1,
                                      unsigned& r2, unsigned& r3, uint32_t addr) {
    asm volatile("ldmatrix.sync.aligned.m8n8.x4.shared.b16 {%0,%1,%2,%3}, [%4];"
                 : "=r"(r0), "=r"(r1), "=r"(r2), "=r"(r3) : "r"(addr));
}

// ---------------------------------------------------------------------------
// Prologue: round hidden (grid-stride) + ONE merged transpose kernel
// ---------------------------------------------------------------------------
__global__ void round_tf32(const float* __restrict__ src, float* __restrict__ dst, int n4)
{
    for (int i = blockIdx.x * blockDim.x + threadIdx.x; i < n4; i += gridDim.x * blockDim.x) {
        float4 v = ((const float4*)src)[i];
        v.x = tf32r(v.x); v.y = tf32r(v.y); v.z = tf32r(v.z); v.w = tf32r(v.w);
        ((float4*)dst)[i] = v;
    }
}

// Merged transpose: blockIdx.z selects (src,dst,Kd,Nd) segment.
// dst[n*Kd + k] = tf32r(src[k*Nd + n])
__global__ void transpose_all(const float* __restrict__ wq, const float* __restrict__ wk,
                              const float* __restrict__ wv, const float* __restrict__ wo)
{
    __shared__ float t[32][33];
    const float* src;
    float* dst;
    int Kd, Nd;
    int seg = blockIdx.z;
    if (seg == 0)      { src = wq; dst = g_wqt; Kd = HIDDEN;  Nd = NH * HD; }
    else if (seg == 1) { src = wk; dst = g_wkt; Kd = HIDDEN;  Nd = NKV * HD; }
    else if (seg == 2) { src = wv; dst = g_wvt; Kd = HIDDEN;  Nd = NKV * HD; }
    else               { src = wo; dst = g_wot; Kd = NH * HD; Nd = HIDDEN; }

    const int n0 = blockIdx.x * 32, k0 = blockIdx.y * 32;
    if (n0 >= Nd || k0 >= Kd) return;
    const int tx = threadIdx.x, ty = threadIdx.y;
#pragma unroll
    for (int i = 0; i < 4; i++)
        t[ty + i * 8][tx] = src[(size_t)(k0 + ty + i * 8) * Nd + n0 + tx];
    __syncthreads();
#pragma unroll
    for (int i = 0; i < 4; i++)
        dst[(size_t)(n0 + ty + i * 8) * Kd + k0 + tx] = tf32r(t[tx][ty + i * 8]);
}

// ---------------------------------------------------------------------------
// GEMM mainloop v3 (unchanged from R8): 128x128 tile, BK=32, 3-stage cp.async,
// XOR-swizzled smem. Both fragments via ldmatrix.
// ---------------------------------------------------------------------------
#define STAGE_B 16384u
#define GEMM_SMEM (6 * 16384)

template<int WARPS_M>
__device__ __forceinline__ void gemm_mainloop3(
    const float* __restrict__ Ag, const float* __restrict__ Bg,
    int K, float (*acc)[4])
{
    extern __shared__ float smem[];
    constexpr int MT = 8 / WARPS_M;
    constexpr int NT = 2 * WARPS_M;
    constexpr int NPAIR = NT / 2;

    const int tid  = threadIdx.x;
    const int lane = tid & 31;
    const int warp = tid >> 5;
    const int wm   = warp % WARPS_M;
    const int wn   = warp / WARPS_M;

    const uint32_t sA = (uint32_t)__cvta_generic_to_shared(smem);
    const uint32_t sB = sA + 3 * STAGE_B;

    const int lrow = tid >> 3;
    const int lj   = tid & 7;
    const uint32_t wsw = (uint32_t)((lj ^ (lrow & 7)) << 4);

    const int frow = ((lane >> 3) & 1) * 8 + (lane & 7);
    const int fjb  = lane >> 4;
    const int axr  = frow & 7;
    const uint32_t arowb = (uint32_t)((wm * MT * 16 + frow) * 128);
    const int brow = (lane & 7) + ((lane >> 4) & 1) * 8;
    const int bjb  = (lane >> 3) & 1;
    const int bxr  = brow & 7;
    const uint32_t browb = (uint32_t)((wn * NT * 8 + brow) * 128);

#define ISSUE(kc, st) do {                                                           \
    _Pragma("unroll")                                                                \
    for (int i = 0; i < 4; i++) {                                                    \
        const int r = lrow + 32 * i;                                                 \
        const float* sa = Ag + (size_t)r * K + (kc) * 32 + lj * 4;                   \
        const uint32_t da = sA + (uint32_t)(st) * STAGE_B + (uint32_t)(r * 128) + wsw; \
        asm volatile("cp.async.cg.shared.global [%0], [%1], 16;" :: "r"(da), "l"(sa)); \
    }                                                                                \
    _Pragma("unroll")                                                                \
    for (int i = 0; i < 4; i++) {                                                    \
        const int r = lrow + 32 * i;                                                 \
        const float* sb = Bg + (size_t)r * K + (kc) * 32 + lj * 4;                   \
        const uint32_t db = sB + (uint32_t)(st) * STAGE_B + (uint32_t)(r * 128) + wsw; \
        asm volatile("cp.async.cg.shared.global [%0], [%1], 16;" :: "r"(db), "l"(sb)); \
    }                                                                                \
    asm volatile("cp.async.commit_group;");                                          \
} while (0)

    const int nkc = K >> 5;
    ISSUE(0, 0);
    ISSUE(1, 1);

    for (int kc = 0; kc < nkc; kc++) {
        if (kc < nkc - 1) asm volatile("cp.async.wait_group 1;");
        else              asm volatile("cp.async.wait_group 0;");
        __syncthreads();

        const int st = kc % 3;
        const uint32_t aS = sA + (uint32_t)st * STAGE_B;
        const uint32_t bS = sB + (uint32_t)st * STAGE_B;

#pragma unroll
        for (int ks = 0; ks < 4; ks++) {
            unsigned a[MT][4];
#pragma unroll
            for (int mt = 0; mt < MT; mt++)
                ldsm4(a[mt][0], a[mt][1], a[mt][2], a[mt][3],
                      aS + arowb + (uint32_t)(mt * 2048)
                         + (uint32_t)((((2 * ks + fjb) ^ axr)) << 4));
#pragma unroll
            for (int ntp = 0; ntp < NPAIR; ntp++) {
                unsigned b0, b1, b2, b3;
                ldsm4(b0, b1, b2, b3,
                      bS + browb + (uint32_t)(ntp * 2048)
                         + (uint32_t)((((2 * ks + bjb) ^ bxr)) << 4));
#pragma unroll
                for (int mt = 0; mt < MT; mt++) {
                    mma8(acc[mt * NT + 2 * ntp],     a[mt][0], a[mt][1], a[mt][2], a[mt][3], b0, b1);
                    mma8(acc[mt * NT + 2 * ntp + 1], a[mt][0], a[mt][1], a[mt][2], a[mt][3], b2, b3);
                }
            }
        }
        if (kc + 2 < nkc) ISSUE(kc + 2, (kc + 2) % 3);
    }
#undef ISSUE
}

// ---------------------------------------------------------------------------
// Fused QKV projection + RoPE epilogue (unchanged from R8).
// ---------------------------------------------------------------------------
__global__ __launch_bounds__(256, 2)
void qkv_gemm()
{
    const int bx = blockIdx.x, by = blockIdx.y;
    const int tid = threadIdx.x;
    const int lane = tid & 31, warp = tid >> 5;
    const int wm = warp % 4, wn = warp / 4;
    const int q = lane & 3, g = lane >> 2;

    const float* W;
    float* Out;
    int cb, heads;
    bool rope;
    float oscale;
    if (bx < 16)      { W = g_wqt; Out = g_q; cb = bx * 128;        heads = NH;  rope = true;  oscale = 0.125f; }
    else if (bx < 20) { W = g_wkt; Out = g_k; cb = (bx - 16) * 128; heads = NKV; rope = true;  oscale = 1.0f; }
    else              { W = g_wvt; Out = g_v; cb = (bx - 20) * 128; heads = NKV; rope = false; oscale = 1.0f; }

    float acc[16][4];
#pragma unroll
    for (int i = 0; i < 16; i++)
#pragma unroll
        for (int j = 0; j < 4; j++) acc[i][j] = 0.0f;

    gemm_mainloop3<4>(g_ht + (size_t)(by * 128) * HIDDEN,
                      W + (size_t)cb * HIDDEN, HIDDEN, acc);

    if (rope) {
        float invf[8];
#pragma unroll
        for (int ntp = 0; ntp < 4; ntp++)
#pragma unroll
            for (int j = 0; j < 2; j++)
                invf[ntp * 2 + j] =
                    powf(10000.0f, -((float)(2 * (ntp * 8 + (q << 1) + j)) / 64.0f));
#pragma unroll
        for (int mt = 0; mt < 2; mt++) {
#pragma unroll
            for (int rh = 0; rh < 2; rh++) {
                const int m = by * 128 + wm * 32 + mt * 16 + g + rh * 8;
                const float s = (float)(m & (SEQ - 1));
#pragma unroll
                for (int ntp = 0; ntp < 4; ntp++) {
#pragma unroll
                    for (int j = 0; j < 2; j++) {
                        float c, si;
                        sincosf(s * invf[ntp * 2 + j], &si, &c);
                        const float x1 = acc[mt * 8 + ntp][rh * 2 + j];
                        const float x2 = acc[mt * 8 + ntp + 4][rh * 2 + j];
                        acc[mt * 8 + ntp][rh * 2 + j]     = x1 * c - x2 * si;
                        acc[mt * 8 + ntp + 4][rh * 2 + j] = x2 * c + x1 * si;
                    }
                }
            }
        }
    }

#pragma unroll
    for (int mt = 0; mt < 2; mt++) {
        const int row = by * 128 + wm * 32 + mt * 16 + g;
#pragma unroll
        for (int nt = 0; nt < 8; nt++) {
            const int col = cb + wn * 64 + nt * 8 + (q << 1);
            const int hh = col / HD, dd = col & (HD - 1);
#pragma unroll
            for (int rh = 0; rh < 2; rh++) {
                const int m = row + rh * 8;
                const int bb = m >> 11, ss = m & (SEQ - 1);
                float* p = Out + (((size_t)bb * heads + hh) * SEQ + ss) * HD + dd;
                p[0] = tf32r(acc[mt * 8 + nt][rh * 2]     * oscale);
                p[1] = tf32r(acc[mt * 8 + nt][rh * 2 + 1] * oscale);
            }
        }
    }
}

// ---------------------------------------------------------------------------
// Output projection (unchanged from R8)
// ---------------------------------------------------------------------------
__global__ __launch_bounds__(256, 2)
void gemm_o(float* __restrict__ C)
{
    const int bx = blockIdx.x, by = blockIdx.y;
    const int tid = threadIdx.x;
    const int lane = tid & 31, warp = tid >> 5;
    const int wm = warp % 2, wn = warp / 2;
    const int q = lane & 3, g = lane >> 2;

    float acc[16][4];
#pragma unroll
    for (int i = 0; i < 16; i++)
#pragma unroll
        for (int j = 0; j < 4; j++) acc[i][j] = 0.0f;

    gemm_mainloop3<2>(g_attn + (size_t)(by * 128) * HIDDEN,
                      g_wot + (size_t)(bx * 128) * HIDDEN, HIDDEN, acc);

#pragma unroll
    for (int mt = 0; mt < 4; mt++) {
        const int row = by * 128 + wm * 64 + mt * 16 + g;
#pragma unroll
        for (int nt = 0; nt < 4; nt++) {
            const int col = bx * 128 + wn * 32 + nt * 8 + (q << 1);
            *(float2*)(C + (size_t)row * HIDDEN + col) =
                make_float2(acc[mt * 4 + nt][0], acc[mt * 4 + nt][1]);
            *(float2*)(C + (size_t)(row + 8) * HIDDEN + col) =
                make_float2(acc[mt * 4 + nt][2], acc[mt * 4 + nt][3]);
        }
    }
}

// ---------------------------------------------------------------------------
// Flash attention (R8-proven shape): 64-row Q tiles, 4 warps, occ 3,
// cp.async K/V alternating pipeline, K/P via ldsm4, V scalar, Ps aliases Qs.
// Only change vs R8: qb-reversed launch order (heavy blocks first).
// ---------------------------------------------------------------------------
#define QSTR 68
#define VSTR 72
#define FLASH_SMEM ((64 * QSTR * 2 + 64 * VSTR) * 4)

__global__ __launch_bounds__(128, 3)
void flash_tf32(const float* __restrict__ Q, const float* __restrict__ K,
                const float* __restrict__ V, float* __restrict__ O)
{
    extern __shared__ float sm[];
    float* Qs = sm;
    float* Ks = Qs + 64 * QSTR;
    float* Vs = Ks + 64 * QSTR;
    float* Ps = Qs;

    const int qb   = gridDim.x - 1 - blockIdx.x;   // heavy blocks first
    const int h    = blockIdx.y;
    const int b    = blockIdx.z;
    const int tid  = threadIdx.x;
    const int lane = tid & 31;
    const int warp = tid >> 5;
    const int q    = lane & 3;
    const int g    = lane >> 2;

    const float* Qg = Q + (((size_t)b * NH + h) * SEQ + qb * 64) * HD;
    const float* Kg = K + ((size_t)b * NKV + h / NREP) * SEQ * HD;
    const float* Vg = V + ((size_t)b * NKV + h / NREP) * SEQ * HD;

    const uint32_t sKs = (uint32_t)__cvta_generic_to_shared(Ks);
    const uint32_t sVs = (uint32_t)__cvta_generic_to_shared(Vs);
    const uint32_t sPs = (uint32_t)__cvta_generic_to_shared(Ps);

    auto issue_k = [&](int kt) {
#pragma unroll
        for (int i = 0; i < 8; i++) {
            const int f = tid + 128 * i;
            const int r = f >> 4, c4 = (f & 15) << 2;
            const uint32_t d = sKs + (uint32_t)((r * QSTR + c4) * 4);
            const float* s = Kg + (size_t)kt * 64 * HD + f * 4;
            asm volatile("cp.async.cg.shared.global [%0], [%1], 16;" :: "r"(d), "l"(s));
        }
        asm volatile("cp.async.commit_group;");
    };
    auto issue_v = [&](int kt) {
#pragma unroll
        for (int i = 0; i < 8; i++) {
            const int f = tid + 128 * i;
            const int r = f >> 4, c4 = (f & 15) << 2;
            const uint32_t d = sVs + (uint32_t)((r * VSTR + c4) * 4);
            const float* s = Vg + (size_t)kt * 64 * HD + f * 4;
            asm volatile("cp.async.cg.shared.global [%0], [%1], 16;" :: "r"(d), "l"(s));
        }
        asm volatile("cp.async.commit_group;");
    };

    issue_k(0);
    issue_v(0);

#pragma unroll
    for (int i = 0; i < 8; i++) {
        const int f = tid + 128 * i;
        const int r = f >> 4, c4 = (f & 15) << 2;
        *(float4*)&Qs[r * QSTR + c4] = *(const float4*)&Qg[r * HD + c4];
    }
    __syncthreads();

    const int rA = warp * 16 + g;

    unsigned qf[8][4];
#pragma unroll
    for (int ks = 0; ks < 8; ks++) {
        const int k0 = ks * 8;
        qf[ks][0] = F2U(Qs[rA * QSTR + k0 + q]);
        qf[ks][1] = F2U(Qs[(rA + 8) * QSTR + k0 + q]);
        qf[ks][2] = F2U(Qs[rA * QSTR + k0 + 4 + q]);
        qf[ks][3] = F2U(Qs[(rA + 8) * QSTR + k0 + 4 + q]);
    }

    const int arow = ((lane >> 3) & 1) * 8 + (lane & 7);
    const int acol = (lane >> 4) * 4;
    const uint32_t pbase = sPs + (uint32_t)(((warp * 16 + arow) * QSTR + acol) * 4);
    const int krow = (lane & 7) + ((lane >> 4) & 1) * 8;
    const int kcol = ((lane >> 3) & 1) * 4;
    const uint32_t kf4 = sKs + (uint32_t)((krow * QSTR + kcol) * 4);

    float m_i[2], l_i[2], o_acc[8][4];
#pragma unroll
    for (int rh = 0; rh < 2; rh++) { m_i[rh] = -INFINITY; l_i[rh] = 0.0f; }
#pragma unroll
    for (int nt = 0; nt < 8; nt++)
#pragma unroll
        for (int j = 0; j < 4; j++) o_acc[nt][j] = 0.0f;

    for (int kt = 0; kt <= qb; kt++) {
        asm volatile("cp.async.wait_group 1;");
        __syncthreads();

        float s_acc[8][4];
#pragma unroll
        for (int nt = 0; nt < 8; nt++)
#pragma unroll
            for (int j = 0; j < 4; j++) s_acc[nt][j] = 0.0f;

#pragma unroll
        for (int ks = 0; ks < 8; ks++) {
#pragma unroll
            for (int ntp = 0; ntp < 4; ntp++) {
                unsigned b0, b1, b2, b3;
                ldsm4(b0, b1, b2, b3, kf4 + (uint32_t)((ntp * 16 * QSTR + ks * 8) * 4));
                mma8(s_acc[2 * ntp],     qf[ks][0], qf[ks][1], qf[ks][2], qf[ks][3], b0, b1);
                mma8(s_acc[2 * ntp + 1], qf[ks][0], qf[ks][1], qf[ks][2], qf[ks][3], b2, b3);
            }
        }

        const bool diag = (kt == qb);

#pragma unroll
        for (int rh = 0; rh < 2; rh++) {
            const int rg = qb * 64 + rA + rh * 8;
            float mx = -INFINITY;
#pragma unroll
            for (int nt = 0; nt < 8; nt++) {
#pragma unroll
                for (int j = 0; j < 2; j++) {
                    float sv = s_acc[nt][rh * 2 + j];
                    if (diag) {
                        int cg = kt * 64 + nt * 8 + (q << 1) + j;
                        if (cg > rg) sv = -INFINITY;
                    }
                    s_acc[nt][rh * 2 + j] = sv;
                    mx = fmaxf(mx, sv);
                }
            }
            mx = fmaxf(mx, __shfl_xor_sync(0xffffffffu, mx, 1));
            mx = fmaxf(mx, __shfl_xor_sync(0xffffffffu, mx, 2));

            const float mnew = fmaxf(m_i[rh], mx);
            const float sc = __expf(m_i[rh] - mnew);
            m_i[rh] = mnew;

            float rs = 0.0f;
#pragma unroll
            for (int nt = 0; nt < 8; nt++) {
#pragma unroll
                for (int j = 0; j < 2; j++) {
                    float p = __expf(s_acc[nt][rh * 2 + j] - mnew);
                    s_acc[nt][rh * 2 + j] = p;
                    rs += p;
                }
            }
            rs += __shfl_xor_sync(0xffffffffu, rs, 1);
            rs += __shfl_xor_sync(0xffffffffu, rs, 2);

            l_i[rh] = l_i[rh] * sc + rs;
#pragma unroll
            for (int nt = 0; nt < 8; nt++) {
                o_acc[nt][rh * 2]     *= sc;
                o_acc[nt][rh * 2 + 1] *= sc;
            }
        }

#pragma unroll
        for (int nt = 0; nt < 8; nt++) {
            const int c = nt * 8 + (q << 1);
            Ps[rA * QSTR + c]           = tf32r(s_acc[nt][0]);
            Ps[rA * QSTR + c + 1]       = tf32r(s_acc[nt][1]);
            Ps[(rA + 8) * QSTR + c]     = tf32r(s_acc[nt][2]);
            Ps[(rA + 8) * QSTR + c + 1] = tf32r(s_acc[nt][3]);
        }
        __syncwarp();

        asm volatile("cp.async.wait_group 0;");
        __syncthreads();
        if (kt < qb) issue_k(kt + 1);

#pragma unroll
        for (int ks = 0; ks < 8; ks++) {
            const int k0 = ks * 8;
            unsigned a0, a1, a2, a3;
            ldsm4(a0, a1, a2, a3, pbase + (uint32_t)(k0 * 4));
#pragma unroll
            for (int nt = 0; nt < 8; nt++) {
                const int n = nt * 8 + g;
                const unsigned b0 = F2U(Vs[(k0 + q) * VSTR + n]);
                const unsigned b1 = F2U(Vs[(k0 + 4 + q) * VSTR + n]);
                mma8(o_acc[nt], a0, a1, a2, a3, b0, b1);
            }
        }
        __syncthreads();
        if (kt < qb) issue_v(kt + 1);
    }

    const float inv0 = 1.0f / l_i[0];
    const float inv1 = 1.0f / l_i[1];
#pragma unroll
    for (int nt = 0; nt < 8; nt++) {
        const int c = nt * 8 + (q << 1);
        const int r0 = qb * 64 + rA;
        float* p0 = O + ((size_t)b * SEQ + r0) * (NH * HD) + h * HD + c;
        p0[0] = tf32r(o_acc[nt][0] * inv0);
        p0[1] = tf32r(o_acc[nt][1] * inv0);
        float* p1 = O + ((size_t)b * SEQ + r0 + 8) * (NH * HD) + h * HD + c;
        p1[0] = tf32r(o_acc[nt][2] * inv1);
        p1[1] = tf32r(o_acc[nt][3] * inv1);
    }
}

// ---------------------------------------------------------------------------
// kernel_launch
// ---------------------------------------------------------------------------
extern "C" void kernel_launch(void* const* d_in, const int* in_sizes, int n_in,
                              void* d_out, int out_size)
{
    const float* hidden = (const float*)d_in[0];
    const float* wq = (const float*)d_in[1];
    const float* wk = (const float*)d_in[2];
    const float* wv = (const float*)d_in[3];
    const float* wo = (const float*)d_in[4];
    float* out = (float*)d_out;

    float *pq, *pk, *pv, *pattn, *pht;
    cudaGetSymbolAddress((void**)&pq, g_q);
    cudaGetSymbolAddress((void**)&pk, g_k);
    cudaGetSymbolAddress((void**)&pv, g_v);
    cudaGetSymbolAddress((void**)&pattn, g_attn);
    cudaGetSymbolAddress((void**)&pht, g_ht);

    const int M = BSZ * SEQ;   // 4096

    cudaFuncSetAttribute(qkv_gemm, cudaFuncAttributeMaxDynamicSharedMemorySize, GEMM_SMEM);
    cudaFuncSetAttribute(gemm_o, cudaFuncAttributeMaxDynamicSharedMemorySize, GEMM_SMEM);
    cudaFuncSetAttribute(flash_tf32, cudaFuncAttributeMaxDynamicSharedMemorySize, FLASH_SMEM);

    // 1) round hidden; merged transpose+round of all weights to [N,K]
    const int nh4 = BSZ * SEQ * HIDDEN / 4;
    round_tf32<<<1184, 256>>>(hidden, pht, nh4);
    transpose_all<<<dim3(HIDDEN / 32, HIDDEN / 32, 4), dim3(32, 8)>>>(wq, wk, wv, wo);

    // 2) fused QKV projection + RoPE (24 N-tiles: 16 Q, 4 K, 4 V)
    qkv_gemm<<<dim3(24, M / 128), dim3(256), GEMM_SMEM>>>();

    // 3) flash attention (qb-reversed launch order)
    flash_tf32<<<dim3(SEQ / 64, NH, BSZ), dim3(128), FLASH_SMEM>>>(pq, pk, pv, pattn);

    // 4) output projection
    gemm_o<<<dim3(HIDDEN / 128, M / 128), dim3(256), GEMM_SMEM>>>(out);
}

// round 11
// speedup vs baseline: 1.6253x; 1.0046x over previous
#include <cuda_runtime.h>
#include <math.h>
#include <stdint.h>

#define BSZ 2
#define SEQ 2048
#define HIDDEN 2048
#define NH 32
#define NKV 8
#define HD 64
#define NREP 4

// Scratch (static device arrays — no allocation).
__device__ float g_q[BSZ * NH * SEQ * HD];      // [b, h, s, d] tf32-rounded, pre-scaled 1/8
__device__ float g_k[BSZ * NKV * SEQ * HD];     // [b, kvh, s, d] tf32-rounded
__device__ float g_v[BSZ * NKV * HD * SEQ];     // [b, kvh, d, s] (TRANSPOSED) tf32-rounded
__device__ float g_attn[BSZ * SEQ * NH * HD];   // [b, s, h*d] tf32-rounded

__device__ float g_ht[BSZ * SEQ * HIDDEN];      // tf32-rounded hidden
__device__ float g_wqt[NH * HD * HIDDEN];       // [N,K] k-major, tf32-rounded
__device__ float g_wkt[NKV * HD * HIDDEN];
__device__ float g_wvt[NKV * HD * HIDDEN];
__device__ float g_wot[HIDDEN * NH * HD];       // [N=2048, K=2048]

// ---------------------------------------------------------------------------
// Helpers
// ---------------------------------------------------------------------------
__device__ __forceinline__ float tf32r(float x) {
    unsigned u;
    asm("cvt.rna.tf32.f32 %0, %1;" : "=r"(u) : "f"(x));
    return __uint_as_float(u);
}
#define F2U __float_as_uint

__device__ __forceinline__ void mma8(float c[4],
                                     unsigned a0, unsigned a1, unsigned a2, unsigned a3,
                                     unsigned b0, unsigned b1) {
    asm volatile(
        "mma.sync.aligned.m16n8k8.row.col.f32.tf32.tf32.f32 "
        "{%0,%1,%2,%3}, {%4,%5,%6,%7}, {%8,%9}, {%0,%1,%2,%3};\n"
        : "+f"(c[0]), "+f"(c[1]), "+f"(c[2]), "+f"(c[3])
        : "r"(a0), "r"(a1), "r"(a2), "r"(a3), "r"(b0), "r"(b1));
}
__device__ __forceinline__ void ldsm4(unsigned& r0, unsigned& r1,
                                      unsigned& r2, unsigned& r3, uint32_t addr) {
    asm volatile("ldmatrix.sync.aligned.m8n8.x4.shared.b16 {%0,%1,%2,%3}, [%4];"
                 : "=r"(r0), "=r"(r1), "=r"(r2), "=r"(r3) : "r"(addr));
}

// ---------------------------------------------------------------------------
// Prologue: round hidden (grid-stride) + ONE merged transpose kernel
// ---------------------------------------------------------------------------
__global__ void round_tf32(const float* __restrict__ src, float* __restrict__ dst, int n4)
{
    for (int i = blockIdx.x * blockDim.x + threadIdx.x; i < n4; i += gridDim.x * blockDim.x) {
        float4 v = ((const float4*)src)[i];
        v.x = tf32r(v.x); v.y = tf32r(v.y); v.z = tf32r(v.z); v.w = tf32r(v.w);
        ((float4*)dst)[i] = v;
    }
}

// Merged transpose: blockIdx.z selects (src,dst,Kd,Nd) segment.
// dst[n*Kd + k] = tf32r(src[k*Nd + n])
__global__ void transpose_all(const float* __restrict__ wq, const float* __restrict__ wk,
                              const float* __restrict__ wv, const float* __restrict__ wo)
{
    __shared__ float t[32][33];
    const float* src;
    float* dst;
    int Kd, Nd;
    int seg = blockIdx.z;
    if (seg == 0)      { src = wq; dst = g_wqt; Kd = HIDDEN;  Nd = NH * HD; }
    else if (seg == 1) { src = wk; dst = g_wkt; Kd = HIDDEN;  Nd = NKV * HD; }
    else if (seg == 2) { src = wv; dst = g_wvt; Kd = HIDDEN;  Nd = NKV * HD; }
    else               { src = wo; dst = g_wot; Kd = NH * HD; Nd = HIDDEN; }

    const int n0 = blockIdx.x * 32, k0 = blockIdx.y * 32;
    if (n0 >= Nd || k0 >= Kd) return;
    const int tx = threadIdx.x, ty = threadIdx.y;
#pragma unroll
    for (int i = 0; i < 4; i++)
        t[ty + i * 8][tx] = src[(size_t)(k0 + ty + i * 8) * Nd + n0 + tx];
    __syncthreads();
#pragma unroll
    for (int i = 0; i < 4; i++)
        dst[(size_t)(n0 + ty + i * 8) * Kd + k0 + tx] = tf32r(t[tx][ty + i * 8]);
}

// ---------------------------------------------------------------------------
// GEMM mainloop v3 (unchanged from R8): 128x128 tile, BK=32, 3-stage cp.async,
// XOR-swizzled smem. Both fragments via ldmatrix.
// ---------------------------------------------------------------------------
#define STAGE_B 16384u
#define GEMM_SMEM (6 * 16384)

template<int WARPS_M>
__device__ __forceinline__ void gemm_mainloop3(
    const float* __restrict__ Ag, const float* __restrict__ Bg,
    int K, float (*acc)[4])
{
    extern __shared__ float smem[];
    constexpr int MT = 8 / WARPS_M;
    constexpr int NT = 2 * WARPS_M;
    constexpr int NPAIR = NT / 2;

    const int tid  = threadIdx.x;
    const int lane = tid & 31;
    const int warp = tid >> 5;
    const int wm   = warp % WARPS_M;
    const int wn   = warp / WARPS_M;

    const uint32_t sA = (uint32_t)__cvta_generic_to_shared(smem);
    const uint32_t sB = sA + 3 * STAGE_B;

    const int lrow = tid >> 3;
    const int lj   = tid & 7;
    const uint32_t wsw = (uint32_t)((lj ^ (lrow & 7)) << 4);

    const int frow = ((lane >> 3) & 1) * 8 + (lane & 7);
    const int fjb  = lane >> 4;
    const int axr  = frow & 7;
    const uint32_t arowb = (uint32_t)((wm * MT * 16 + frow) * 128);
    const int brow = (lane & 7) + ((lane >> 4) & 1) * 8;
    const int bjb  = (lane >> 3) & 1;
    const int bxr  = brow & 7;
    const uint32_t browb = (uint32_t)((wn * NT * 8 + brow) * 128);

#define ISSUE(kc, st) do {                                                           \
    _Pragma("unroll")                                                                \
    for (int i = 0; i < 4; i++) {                                                    \
        const int r = lrow + 32 * i;                                                 \
        const float* sa = Ag + (size_t)r * K + (kc) * 32 + lj * 4;                   \
        const uint32_t da = sA + (uint32_t)(st) * STAGE_B + (uint32_t)(r * 128) + wsw; \
        asm volatile("cp.async.cg.shared.global [%0], [%1], 16;" :: "r"(da), "l"(sa)); \
    }                                                                                \
    _Pragma("unroll")                                                                \
    for (int i = 0; i < 4; i++) {                                                    \
        const int r = lrow + 32 * i;                                                 \
        const float* sb = Bg + (size_t)r * K + (kc) * 32 + lj * 4;                   \
        const uint32_t db = sB + (uint32_t)(st) * STAGE_B + (uint32_t)(r * 128) + wsw; \
        asm volatile("cp.async.cg.shared.global [%0], [%1], 16;" :: "r"(db), "l"(sb)); \
    }                                                                                \
    asm volatile("cp.async.commit_group;");                                          \
} while (0)

    const int nkc = K >> 5;
    ISSUE(0, 0);
    ISSUE(1, 1);

    for (int kc = 0; kc < nkc; kc++) {
        if (kc < nkc - 1) asm volatile("cp.async.wait_group 1;");
        else              asm volatile("cp.async.wait_group 0;");
        __syncthreads();

        const int st = kc % 3;
        const uint32_t aS = sA + (uint32_t)st * STAGE_B;
        const uint32_t bS = sB + (uint32_t)st * STAGE_B;

#pragma unroll
        for (int ks = 0; ks < 4; ks++) {
            unsigned a[MT][4];
#pragma unroll
            for (int mt = 0; mt < MT; mt++)
                ldsm4(a[mt][0], a[mt][1], a[mt][2], a[mt][3],
                      aS + arowb + (uint32_t)(mt * 2048)
                         + (uint32_t)((((2 * ks + fjb) ^ axr)) << 4));
#pragma unroll
            for (int ntp = 0; ntp < NPAIR; ntp++) {
                unsigned b0, b1, b2, b3;
                ldsm4(b0, b1, b2, b3,
                      bS + browb + (uint32_t)(ntp * 2048)
                         + (uint32_t)((((2 * ks + bjb) ^ bxr)) << 4));
#pragma unroll
                for (int mt = 0; mt < MT; mt++) {
                    mma8(acc[mt * NT + 2 * ntp],     a[mt][0], a[mt][1], a[mt][2], a[mt][3], b0, b1);
                    mma8(acc[mt * NT + 2 * ntp + 1], a[mt][0], a[mt][1], a[mt][2], a[mt][3], b2, b3);
                }
            }
        }
        if (kc + 2 < nkc) ISSUE(kc + 2, (kc + 2) % 3);
    }
#undef ISSUE
}

// ---------------------------------------------------------------------------
// Fused QKV projection + RoPE epilogue. V is stored TRANSPOSED [b,kvh,d,s].
// ---------------------------------------------------------------------------
__global__ __launch_bounds__(256, 2)
void qkv_gemm()
{
    const int bx = blockIdx.x, by = blockIdx.y;
    const int tid = threadIdx.x;
    const int lane = tid & 31, warp = tid >> 5;
    const int wm = warp % 4, wn = warp / 4;
    const int q = lane & 3, g = lane >> 2;

    const float* W;
    float* Out;
    int cb, heads;
    bool rope;
    float oscale;
    if (bx < 16)      { W = g_wqt; Out = g_q; cb = bx * 128;        heads = NH;  rope = true;  oscale = 0.125f; }
    else if (bx < 20) { W = g_wkt; Out = g_k; cb = (bx - 16) * 128; heads = NKV; rope = true;  oscale = 1.0f; }
    else              { W = g_wvt; Out = g_v; cb = (bx - 20) * 128; heads = NKV; rope = false; oscale = 1.0f; }

    float acc[16][4];
#pragma unroll
    for (int i = 0; i < 16; i++)
#pragma unroll
        for (int j = 0; j < 4; j++) acc[i][j] = 0.0f;

    gemm_mainloop3<4>(g_ht + (size_t)(by * 128) * HIDDEN,
                      W + (size_t)cb * HIDDEN, HIDDEN, acc);

    if (rope) {
        float invf[8];
#pragma unroll
        for (int ntp = 0; ntp < 4; ntp++)
#pragma unroll
            for (int j = 0; j < 2; j++)
                invf[ntp * 2 + j] =
                    powf(10000.0f, -((float)(2 * (ntp * 8 + (q << 1) + j)) / 64.0f));
#pragma unroll
        for (int mt = 0; mt < 2; mt++) {
#pragma unroll
            for (int rh = 0; rh < 2; rh++) {
                const int m = by * 128 + wm * 32 + mt * 16 + g + rh * 8;
                const float s = (float)(m & (SEQ - 1));
#pragma unroll
                for (int ntp = 0; ntp < 4; ntp++) {
#pragma unroll
                    for (int j = 0; j < 2; j++) {
                        float c, si;
                        sincosf(s * invf[ntp * 2 + j], &si, &c);
                        const float x1 = acc[mt * 8 + ntp][rh * 2 + j];
                        const float x2 = acc[mt * 8 + ntp + 4][rh * 2 + j];
                        acc[mt * 8 + ntp][rh * 2 + j]     = x1 * c - x2 * si;
                        acc[mt * 8 + ntp + 4][rh * 2 + j] = x2 * c + x1 * si;
                    }
                }
            }
        }
    }

#pragma unroll
    for (int mt = 0; mt < 2; mt++) {
        const int row = by * 128 + wm * 32 + mt * 16 + g;
#pragma unroll
        for (int nt = 0; nt < 8; nt++) {
            const int col = cb + wn * 64 + nt * 8 + (q << 1);
            const int hh = col / HD, dd = col & (HD - 1);
#pragma unroll
            for (int rh = 0; rh < 2; rh++) {
                const int m = row + rh * 8;
                const int bb = m >> 11, ss = m & (SEQ - 1);
                if (rope) {
                    // Q, K: [b, h, s, d]
                    float* p = Out + (((size_t)bb * heads + hh) * SEQ + ss) * HD + dd;
                    p[0] = tf32r(acc[mt * 8 + nt][rh * 2]     * oscale);
                    p[1] = tf32r(acc[mt * 8 + nt][rh * 2 + 1] * oscale);
                } else {
                    // V: transposed [b, kvh, d, s]
                    float* p = Out + (((size_t)bb * heads + hh) * HD + dd) * SEQ + ss;
                    p[0]   = tf32r(acc[mt * 8 + nt][rh * 2]);
                    p[SEQ] = tf32r(acc[mt * 8 + nt][rh * 2 + 1]);
                }
            }
        }
    }
}

// ---------------------------------------------------------------------------
// Output projection (unchanged from R8)
// ---------------------------------------------------------------------------
__global__ __launch_bounds__(256, 2)
void gemm_o(float* __restrict__ C)
{
    const int bx = blockIdx.x, by = blockIdx.y;
    const int tid = threadIdx.x;
    const int lane = tid & 31, warp = tid >> 5;
    const int wm = warp % 2, wn = warp / 2;
    const int q = lane & 3, g = lane >> 2;

    float acc[16][4];
#pragma unroll
    for (int i = 0; i < 16; i++)
#pragma unroll
        for (int j = 0; j < 4; j++) acc[i][j] = 0.0f;

    gemm_mainloop3<2>(g_attn + (size_t)(by * 128) * HIDDEN,
                      g_wot + (size_t)(bx * 128) * HIDDEN, HIDDEN, acc);

#pragma unroll
    for (int mt = 0; mt < 4; mt++) {
        const int row = by * 128 + wm * 64 + mt * 16 + g;
#pragma unroll
        for (int nt = 0; nt < 4; nt++) {
            const int col = bx * 128 + wn * 32 + nt * 8 + (q << 1);
            *(float2*)(C + (size_t)row * HIDDEN + col) =
                make_float2(acc[mt * 4 + nt][0], acc[mt * 4 + nt][1]);
            *(float2*)(C + (size_t)(row + 8) * HIDDEN + col) =
                make_float2(acc[mt * 4 + nt][2], acc[mt * 4 + nt][3]);
        }
    }
}

// ---------------------------------------------------------------------------
// Flash attention: 64-row Q tiles, 4 warps, occ 3, cp.async K/V pipeline.
// V now arrives TRANSPOSED [d][key] -> PV B-fragments via ldsm4 (same pattern
// as K in the S phase). Per-warp-tile shared ops: 32+8+32 ldsm4 + 32 STS
// (was +128 scalar LDS). Ps aliases Qs. Heavy blocks launch first.
// ---------------------------------------------------------------------------
#define QSTR 68
#define FLASH_SMEM ((64 * QSTR * 3) * 4)

__global__ __launch_bounds__(128, 3)
void flash_tf32(const float* __restrict__ Q, const float* __restrict__ K,
                const float* __restrict__ V, float* __restrict__ O)
{
    extern __shared__ float sm[];
    float* Qs = sm;
    float* Ks = Qs + 64 * QSTR;
    float* Vs = Ks + 64 * QSTR;       // [64 d][QSTR] (transposed V tile)
    float* Ps = Qs;

    const int qb   = gridDim.x - 1 - blockIdx.x;   // heavy blocks first
    const int h    = blockIdx.y;
    const int b    = blockIdx.z;
    const int tid  = threadIdx.x;
    const int lane = tid & 31;
    const int warp = tid >> 5;
    const int q    = lane & 3;
    const int g    = lane >> 2;

    const float* Qg = Q + (((size_t)b * NH + h) * SEQ + qb * 64) * HD;
    const float* Kg = K + ((size_t)b * NKV + h / NREP) * SEQ * HD;
    const float* Vg = V + ((size_t)b * NKV + h / NREP) * HD * SEQ;  // [d][s]

    const uint32_t sKs = (uint32_t)__cvta_generic_to_shared(Ks);
    const uint32_t sVs = (uint32_t)__cvta_generic_to_shared(Vs);
    const uint32_t sPs = (uint32_t)__cvta_generic_to_shared(Ps);

    auto issue_k = [&](int kt) {
#pragma unroll
        for (int i = 0; i < 8; i++) {
            const int f = tid + 128 * i;
            const int r = f >> 4, c4 = (f & 15) << 2;
            const uint32_t d = sKs + (uint32_t)((r * QSTR + c4) * 4);
            const float* s = Kg + (size_t)kt * 64 * HD + f * 4;
            asm volatile("cp.async.cg.shared.global [%0], [%1], 16;" :: "r"(d), "l"(s));
        }
        asm volatile("cp.async.commit_group;");
    };
    // V tile: 64 d-rows x 64 keys from [d][s]; row r contiguous at Vg + r*SEQ + kt*64
    auto issue_v = [&](int kt) {
#pragma unroll
        for (int i = 0; i < 8; i++) {
            const int f = tid + 128 * i;
            const int r = f >> 4, c4 = (f & 15) << 2;
            const uint32_t d = sVs + (uint32_t)((r * QSTR + c4) * 4);
            const float* s = Vg + (size_t)r * SEQ + kt * 64 + c4;
            asm volatile("cp.async.cg.shared.global [%0], [%1], 16;" :: "r"(d), "l"(s));
        }
        asm volatile("cp.async.commit_group;");
    };

    issue_k(0);
    issue_v(0);

#pragma unroll
    for (int i = 0; i < 8; i++) {
        const int f = tid + 128 * i;
        const int r = f >> 4, c4 = (f & 15) << 2;
        *(float4*)&Qs[r * QSTR + c4] = *(const float4*)&Qg[r * HD + c4];
    }
    __syncthreads();

    const int rA = warp * 16 + g;

    unsigned qf[8][4];
#pragma unroll
    for (int ks = 0; ks < 8; ks++) {
        const int k0 = ks * 8;
        qf[ks][0] = F2U(Qs[rA * QSTR + k0 + q]);
        qf[ks][1] = F2U(Qs[(rA + 8) * QSTR + k0 + q]);
        qf[ks][2] = F2U(Qs[rA * QSTR + k0 + 4 + q]);
        qf[ks][3] = F2U(Qs[(rA + 8) * QSTR + k0 + 4 + q]);
    }

    // ldmatrix bases
    const int arow = ((lane >> 3) & 1) * 8 + (lane & 7);
    const int acol = (lane >> 4) * 4;
    const uint32_t pbase = sPs + (uint32_t)(((warp * 16 + arow) * QSTR + acol) * 4);
    const int krow = (lane & 7) + ((lane >> 4) & 1) * 8;
    const int kcol = ((lane >> 3) & 1) * 4;
    const uint32_t kf4 = sKs + (uint32_t)((krow * QSTR + kcol) * 4);
    const uint32_t vf4 = sVs + (uint32_t)((krow * QSTR + kcol) * 4);

    float m_i[2], l_i[2], o_acc[8][4];
#pragma unroll
    for (int rh = 0; rh < 2; rh++) { m_i[rh] = -INFINITY; l_i[rh] = 0.0f; }
#pragma unroll
    for (int nt = 0; nt < 8; nt++)
#pragma unroll
        for (int j = 0; j < 4; j++) o_acc[nt][j] = 0.0f;

    for (int kt = 0; kt <= qb; kt++) {
        asm volatile("cp.async.wait_group 1;");
        __syncthreads();

        float s_acc[8][4];
#pragma unroll
        for (int nt = 0; nt < 8; nt++)
#pragma unroll
            for (int j = 0; j < 4; j++) s_acc[nt][j] = 0.0f;

#pragma unroll
        for (int ks = 0; ks < 8; ks++) {
#pragma unroll
            for (int ntp = 0; ntp < 4; ntp++) {
                unsigned b0, b1, b2, b3;
                ldsm4(b0, b1, b2, b3, kf4 + (uint32_t)((ntp * 16 * QSTR + ks * 8) * 4));
                mma8(s_acc[2 * ntp],     qf[ks][0], qf[ks][1], qf[ks][2], qf[ks][3], b0, b1);
                mma8(s_acc[2 * ntp + 1], qf[ks][0], qf[ks][1], qf[ks][2], qf[ks][3], b2, b3);
            }
        }

        const bool diag = (kt == qb);

#pragma unroll
        for (int rh = 0; rh < 2; rh++) {
            const int rg = qb * 64 + rA + rh * 8;
            float mx = -INFINITY;
#pragma unroll
            for (int nt = 0; nt < 8; nt++) {
#pragma unroll
                for (int j = 0; j < 2; j++) {
                    float sv = s_acc[nt][rh * 2 + j];
                    if (diag) {
                        int cg = kt * 64 + nt * 8 + (q << 1) + j;
                        if (cg > rg) sv = -INFINITY;
                    }
                    s_acc[nt][rh * 2 + j] = sv;
                    mx = fmaxf(mx, sv);
                }
            }
            mx = fmaxf(mx, __shfl_xor_sync(0xffffffffu, mx, 1));
            mx = fmaxf(mx, __shfl_xor_sync(0xffffffffu, mx, 2));

            const float mnew = fmaxf(m_i[rh], mx);
            const float sc = __expf(m_i[rh] - mnew);
            m_i[rh] = mnew;

            float rs = 0.0f;
#pragma unroll
            for (int nt = 0; nt < 8; nt++) {
#pragma unroll
                for (int j = 0; j < 2; j++) {
                    float p = __expf(s_acc[nt][rh * 2 + j] - mnew);
                    s_acc[nt][rh * 2 + j] = p;
                    rs += p;
                }
            }
            rs += __shfl_xor_sync(0xffffffffu, rs, 1);
            rs += __shfl_xor_sync(0xffffffffu, rs, 2);

            l_i[rh] = l_i[rh] * sc + rs;
#pragma unroll
            for (int nt = 0; nt < 8; nt++) {
                o_acc[nt][rh * 2]     *= sc;
                o_acc[nt][rh * 2 + 1] *= sc;
            }
        }

#pragma unroll
        for (int nt = 0; nt < 8; nt++) {
            const int c = nt * 8 + (q << 1);
            Ps[rA * QSTR + c]           = tf32r(s_acc[nt][0]);
            Ps[rA * QSTR + c + 1]       = tf32r(s_acc[nt][1]);
            Ps[(rA + 8) * QSTR + c]     = tf32r(s_acc[nt][2]);
            Ps[(rA + 8) * QSTR + c + 1] = tf32r(s_acc[nt][3]);
        }
        __syncwarp();

        asm volatile("cp.async.wait_group 0;");
        __syncthreads();
        if (kt < qb) issue_k(kt + 1);

        // O += P @ V : A = P (k=key), B = Vt[d][key] via ldsm4 (nt = d-tile)
#pragma unroll
        for (int ks = 0; ks < 8; ks++) {
            const int k0 = ks * 8;
            unsigned a0, a1, a2, a3;
            ldsm4(a0, a1, a2, a3, pbase + (uint32_t)(k0 * 4));
#pragma unroll
            for (int ntp = 0; ntp < 4; ntp++) {
                unsigned b0, b1, b2, b3;
                ldsm4(b0, b1, b2, b3, vf4 + (uint32_t)((ntp * 16 * QSTR + ks * 8) * 4));
                mma8(o_acc[2 * ntp],     a0, a1, a2, a3, b0, b1);
                mma8(o_acc[2 * ntp + 1], a0, a1, a2, a3, b2, b3);
            }
        }
        __syncthreads();
        if (kt < qb) issue_v(kt + 1);
    }

    const float inv0 = 1.0f / l_i[0];
    const float inv1 = 1.0f / l_i[1];
#pragma unroll
    for (int nt = 0; nt < 8; nt++) {
        const int c = nt * 8 + (q << 1);
        const int r0 = qb * 64 + rA;
        float* p0 = O + ((size_t)b * SEQ + r0) * (NH * HD) + h * HD + c;
        p0[0] = tf32r(o_acc[nt][0] * inv0);
        p0[1] = tf32r(o_acc[nt][1] * inv0);
        float* p1 = O + ((size_t)b * SEQ + r0 + 8) * (NH * HD) + h * HD + c;
        p1[0] = tf32r(o_acc[nt][2] * inv1);
        p1[1] = tf32r(o_acc[nt][3] * inv1);
    }
}

// ---------------------------------------------------------------------------
// kernel_launch
// ---------------------------------------------------------------------------
extern "C" void kernel_launch(void* const* d_in, const int* in_sizes, int n_in,
                              void* d_out, int out_size)
{
    const float* hidden = (const float*)d_in[0];
    const float* wq = (const float*)d_in[1];
    const float* wk = (const float*)d_in[2];
    const float* wv = (const float*)d_in[3];
    const float* wo = (const float*)d_in[4];
    float* out = (float*)d_out;

    float *pq, *pk, *pv, *pattn, *pht;
    cudaGetSymbolAddress((void**)&pq, g_q);
    cudaGetSymbolAddress((void**)&pk, g_k);
    cudaGetSymbolAddress((void**)&pv, g_v);
    cudaGetSymbolAddress((void**)&pattn, g_attn);
    cudaGetSymbolAddress((void**)&pht, g_ht);

    const int M = BSZ * SEQ;   // 4096

    cudaFuncSetAttribute(qkv_gemm, cudaFuncAttributeMaxDynamicSharedMemorySize, GEMM_SMEM);
    cudaFuncSetAttribute(gemm_o, cudaFuncAttributeMaxDynamicSharedMemorySize, GEMM_SMEM);
    cudaFuncSetAttribute(flash_tf32, cudaFuncAttributeMaxDynamicSharedMemorySize, FLASH_SMEM);

    // 1) round hidden; merged transpose+round of all weights to [N,K]
    const int nh4 = BSZ * SEQ * HIDDEN / 4;
    round_tf32<<<1184, 256>>>(hidden, pht, nh4);
    transpose_all<<<dim3(HIDDEN / 32, HIDDEN / 32, 4), dim3(32, 8)>>>(wq, wk, wv, wo);

    // 2) fused QKV projection + RoPE (24 N-tiles: 16 Q, 4 K, 4 V-transposed)
    qkv_gemm<<<dim3(24, M / 128), dim3(256), GEMM_SMEM>>>();

    // 3) flash attention (V transposed -> all-ldmatrix PV)
    flash_tf32<<<dim3(SEQ / 64, NH, BSZ), dim3(128), FLASH_SMEM>>>(pq, pk, pv, pattn);

    // 4) output projection
    gemm_o<<<dim3(HIDDEN / 128, M / 128), dim3(256), GEMM_SMEM>>>(out);
}

// round 12
// speedup vs baseline: 1.6765x; 1.0315x over previous
#include <cuda_runtime.h>
#include <math.h>
#include <stdint.h>

#define BSZ 2
#define SEQ 2048
#define HIDDEN 2048
#define NH 32
#define NKV 8
#define HD 64
#define NREP 4

// Scratch (static device arrays — no allocation).
__device__ float g_q[BSZ * NH * SEQ * HD];      // [b, h, s, d] tf32-rounded, pre-scaled 1/8
__device__ float g_k[BSZ * NKV * SEQ * HD];     // [b, kvh, s, d] tf32-rounded
__device__ float g_v[BSZ * NKV * HD * SEQ];     // [b, kvh, d, s] (TRANSPOSED) tf32-rounded
__device__ float g_attn[BSZ * SEQ * NH * HD];   // [b, s, h*d] tf32-rounded

__device__ float g_ht[BSZ * SEQ * HIDDEN];      // tf32-rounded hidden
__device__ float g_wqt[NH * HD * HIDDEN];       // [N,K] k-major, tf32-rounded
__device__ float g_wkt[NKV * HD * HIDDEN];
__device__ float g_wvt[NKV * HD * HIDDEN];
__device__ float g_wot[HIDDEN * NH * HD];       // [N=2048, K=2048]
__device__ float g_rope[SEQ * 64];              // [s][0:32 cos | 32:64 sin]

// ---------------------------------------------------------------------------
// Helpers
// ---------------------------------------------------------------------------
__device__ __forceinline__ float tf32r(float x) {
    unsigned u;
    asm("cvt.rna.tf32.f32 %0, %1;" : "=r"(u) : "f"(x));
    return __uint_as_float(u);
}
#define F2U __float_as_uint

__device__ __forceinline__ void mma8(float c[4],
                                     unsigned a0, unsigned a1, unsigned a2, unsigned a3,
                                     unsigned b0, unsigned b1) {
    asm volatile(
        "mma.sync.aligned.m16n8k8.row.col.f32.tf32.tf32.f32 "
        "{%0,%1,%2,%3}, {%4,%5,%6,%7}, {%8,%9}, {%0,%1,%2,%3};\n"
        : "+f"(c[0]), "+f"(c[1]), "+f"(c[2]), "+f"(c[3])
        : "r"(a0), "r"(a1), "r"(a2), "r"(a3), "r"(b0), "r"(b1));
}
__device__ __forceinline__ void ldsm4(unsigned& r0, unsigned& r1,
                                      unsigned& r2, unsigned& r3, uint32_t addr) {
    asm volatile("ldmatrix.sync.aligned.m8n8.x4.shared.b16 {%0,%1,%2,%3}, [%4];"
                 : "=r"(r0), "=r"(r1), "=r"(r2), "=r"(r3) : "r"(addr));
}

// ---------------------------------------------------------------------------
// Prologue: round hidden; merged transpose; RoPE cos/sin table
// ---------------------------------------------------------------------------
__global__ void round_tf32(const float* __restrict__ src, float* __restrict__ dst, int n4)
{
    for (int i = blockIdx.x * blockDim.x + threadIdx.x; i < n4; i += gridDim.x * blockDim.x) {
        float4 v = ((const float4*)src)[i];
        v.x = tf32r(v.x); v.y = tf32r(v.y); v.z = tf32r(v.z); v.w = tf32r(v.w);
        ((float4*)dst)[i] = v;
    }
}

__global__ void rope_fill()
{
    int idx = blockIdx.x * blockDim.x + threadIdx.x;   // 65536 total
    int s = idx >> 5, p = idx & 31;
    float inv = powf(10000.0f, -((float)(2 * p) / 64.0f));
    float ang = (float)s * inv;
    float c, si;
    sincosf(ang, &si, &c);
    g_rope[s * 64 + p] = c;
    g_rope[s * 64 + 32 + p] = si;
}

// Merged transpose: blockIdx.z selects (src,dst,Kd,Nd) segment.
// dst[n*Kd + k] = tf32r(src[k*Nd + n])
__global__ void transpose_all(const float* __restrict__ wq, const float* __restrict__ wk,
                              const float* __restrict__ wv, const float* __restrict__ wo)
{
    __shared__ float t[32][33];
    const float* src;
    float* dst;
    int Kd, Nd;
    int seg = blockIdx.z;
    if (seg == 0)      { src = wq; dst = g_wqt; Kd = HIDDEN;  Nd = NH * HD; }
    else if (seg == 1) { src = wk; dst = g_wkt; Kd = HIDDEN;  Nd = NKV * HD; }
    else if (seg == 2) { src = wv; dst = g_wvt; Kd = HIDDEN;  Nd = NKV * HD; }
    else               { src = wo; dst = g_wot; Kd = NH * HD; Nd = HIDDEN; }

    const int n0 = blockIdx.x * 32, k0 = blockIdx.y * 32;
    if (n0 >= Nd || k0 >= Kd) return;
    const int tx = threadIdx.x, ty = threadIdx.y;
#pragma unroll
    for (int i = 0; i < 4; i++)
        t[ty + i * 8][tx] = src[(size_t)(k0 + ty + i * 8) * Nd + n0 + tx];
    __syncthreads();
#pragma unroll
    for (int i = 0; i < 4; i++)
        dst[(size_t)(n0 + ty + i * 8) * Kd + k0 + tx] = tf32r(t[tx][ty + i * 8]);
}

// ---------------------------------------------------------------------------
// GEMM mainloop v3 (unchanged from R8): 128x128 tile, BK=32, 3-stage cp.async,
// XOR-swizzled smem. Both fragments via ldmatrix.
// ---------------------------------------------------------------------------
#define STAGE_B 16384u
#define GEMM_SMEM (6 * 16384)

template<int WARPS_M>
__device__ __forceinline__ void gemm_mainloop3(
    const float* __restrict__ Ag, const float* __restrict__ Bg,
    int K, float (*acc)[4])
{
    extern __shared__ float smem[];
    constexpr int MT = 8 / WARPS_M;
    constexpr int NT = 2 * WARPS_M;
    constexpr int NPAIR = NT / 2;

    const int tid  = threadIdx.x;
    const int lane = tid & 31;
    const int warp = tid >> 5;
    const int wm   = warp % WARPS_M;
    const int wn   = warp / WARPS_M;

    const uint32_t sA = (uint32_t)__cvta_generic_to_shared(smem);
    const uint32_t sB = sA + 3 * STAGE_B;

    const int lrow = tid >> 3;
    const int lj   = tid & 7;
    const uint32_t wsw = (uint32_t)((lj ^ (lrow & 7)) << 4);

    const int frow = ((lane >> 3) & 1) * 8 + (lane & 7);
    const int fjb  = lane >> 4;
    const int axr  = frow & 7;
    const uint32_t arowb = (uint32_t)((wm * MT * 16 + frow) * 128);
    const int brow = (lane & 7) + ((lane >> 4) & 1) * 8;
    const int bjb  = (lane >> 3) & 1;
    const int bxr  = brow & 7;
    const uint32_t browb = (uint32_t)((wn * NT * 8 + brow) * 128);

#define ISSUE(kc, st) do {                                                           \
    _Pragma("unroll")                                                                \
    for (int i = 0; i < 4; i++) {                                                    \
        const int r = lrow + 32 * i;                                                 \
        const float* sa = Ag + (size_t)r * K + (kc) * 32 + lj * 4;                   \
        const uint32_t da = sA + (uint32_t)(st) * STAGE_B + (uint32_t)(r * 128) + wsw; \
        asm volatile("cp.async.cg.shared.global [%0], [%1], 16;" :: "r"(da), "l"(sa)); \
    }                                                                                \
    _Pragma("unroll")                                                                \
    for (int i = 0; i < 4; i++) {                                                    \
        const int r = lrow + 32 * i;                                                 \
        const float* sb = Bg + (size_t)r * K + (kc) * 32 + lj * 4;                   \
        const uint32_t db = sB + (uint32_t)(st) * STAGE_B + (uint32_t)(r * 128) + wsw; \
        asm volatile("cp.async.cg.shared.global [%0], [%1], 16;" :: "r"(db), "l"(sb)); \
    }                                                                                \
    asm volatile("cp.async.commit_group;");                                          \
} while (0)

    const int nkc = K >> 5;
    ISSUE(0, 0);
    ISSUE(1, 1);

    for (int kc = 0; kc < nkc; kc++) {
        if (kc < nkc - 1) asm volatile("cp.async.wait_group 1;");
        else              asm volatile("cp.async.wait_group 0;");
        __syncthreads();

        const int st = kc % 3;
        const uint32_t aS = sA + (uint32_t)st * STAGE_B;
        const uint32_t bS = sB + (uint32_t)st * STAGE_B;

#pragma unroll
        for (int ks = 0; ks < 4; ks++) {
            unsigned a[MT][4];
#pragma unroll
            for (int mt = 0; mt < MT; mt++)
                ldsm4(a[mt][0], a[mt][1], a[mt][2], a[mt][3],
                      aS + arowb + (uint32_t)(mt * 2048)
                         + (uint32_t)((((2 * ks + fjb) ^ axr)) << 4));
#pragma unroll
            for (int ntp = 0; ntp < NPAIR; ntp++) {
                unsigned b0, b1, b2, b3;
                ldsm4(b0, b1, b2, b3,
                      bS + browb + (uint32_t)(ntp * 2048)
                         + (uint32_t)((((2 * ks + bjb) ^ bxr)) << 4));
#pragma unroll
                for (int mt = 0; mt < MT; mt++) {
                    mma8(acc[mt * NT + 2 * ntp],     a[mt][0], a[mt][1], a[mt][2], a[mt][3], b0, b1);
                    mma8(acc[mt * NT + 2 * ntp + 1], a[mt][0], a[mt][1], a[mt][2], a[mt][3], b2, b3);
                }
            }
        }
        if (kc + 2 < nkc) ISSUE(kc + 2, (kc + 2) % 3);
    }
#undef ISSUE
}

// ---------------------------------------------------------------------------
// Fused QKV projection + RoPE epilogue (cos/sin from g_rope table).
// V is stored TRANSPOSED [b,kvh,d,s].
// ---------------------------------------------------------------------------
__global__ __launch_bounds__(256, 2)
void qkv_gemm()
{
    const int bx = blockIdx.x, by = blockIdx.y;
    const int tid = threadIdx.x;
    const int lane = tid & 31, warp = tid >> 5;
    const int wm = warp % 4, wn = warp / 4;
    const int q = lane & 3, g = lane >> 2;

    const float* W;
    float* Out;
    int cb, heads;
    bool rope;
    float oscale;
    if (bx < 16)      { W = g_wqt; Out = g_q; cb = bx * 128;        heads = NH;  rope = true;  oscale = 0.125f; }
    else if (bx < 20) { W = g_wkt; Out = g_k; cb = (bx - 16) * 128; heads = NKV; rope = true;  oscale = 1.0f; }
    else              { W = g_wvt; Out = g_v; cb = (bx - 20) * 128; heads = NKV; rope = false; oscale = 1.0f; }

    float acc[16][4];
#pragma unroll
    for (int i = 0; i < 16; i++)
#pragma unroll
        for (int j = 0; j < 4; j++) acc[i][j] = 0.0f;

    gemm_mainloop3<4>(g_ht + (size_t)(by * 128) * HIDDEN,
                      W + (size_t)cb * HIDDEN, HIDDEN, acc);

    if (rope) {
#pragma unroll
        for (int mt = 0; mt < 2; mt++) {
#pragma unroll
            for (int rh = 0; rh < 2; rh++) {
                const int m = by * 128 + wm * 32 + mt * 16 + g + rh * 8;
                const int ss = m & (SEQ - 1);
                const float* rp = g_rope + ss * 64;
#pragma unroll
                for (int ntp = 0; ntp < 4; ntp++) {
                    const int f = ntp * 8 + (q << 1);
                    const float2 cc = *(const float2*)(rp + f);
                    const float2 sn = *(const float2*)(rp + 32 + f);
                    {
                        const float x1 = acc[mt * 8 + ntp][rh * 2];
                        const float x2 = acc[mt * 8 + ntp + 4][rh * 2];
                        acc[mt * 8 + ntp][rh * 2]     = x1 * cc.x - x2 * sn.x;
                        acc[mt * 8 + ntp + 4][rh * 2] = x2 * cc.x + x1 * sn.x;
                    }
                    {
                        const float x1 = acc[mt * 8 + ntp][rh * 2 + 1];
                        const float x2 = acc[mt * 8 + ntp + 4][rh * 2 + 1];
                        acc[mt * 8 + ntp][rh * 2 + 1]     = x1 * cc.y - x2 * sn.y;
                        acc[mt * 8 + ntp + 4][rh * 2 + 1] = x2 * cc.y + x1 * sn.y;
                    }
                }
            }
        }
    }

#pragma unroll
    for (int mt = 0; mt < 2; mt++) {
        const int row = by * 128 + wm * 32 + mt * 16 + g;
#pragma unroll
        for (int nt = 0; nt < 8; nt++) {
            const int col = cb + wn * 64 + nt * 8 + (q << 1);
            const int hh = col / HD, dd = col & (HD - 1);
#pragma unroll
            for (int rh = 0; rh < 2; rh++) {
                const int m = row + rh * 8;
                const int bb = m >> 11, ss = m & (SEQ - 1);
                if (rope) {
                    float* p = Out + (((size_t)bb * heads + hh) * SEQ + ss) * HD + dd;
                    p[0] = tf32r(acc[mt * 8 + nt][rh * 2]     * oscale);
                    p[1] = tf32r(acc[mt * 8 + nt][rh * 2 + 1] * oscale);
                } else {
                    float* p = Out + (((size_t)bb * heads + hh) * HD + dd) * SEQ + ss;
                    p[0]   = tf32r(acc[mt * 8 + nt][rh * 2]);
                    p[SEQ] = tf32r(acc[mt * 8 + nt][rh * 2 + 1]);
                }
            }
        }
    }
}

// ---------------------------------------------------------------------------
// Output projection (unchanged from R8)
// ---------------------------------------------------------------------------
__global__ __launch_bounds__(256, 2)
void gemm_o(float* __restrict__ C)
{
    const int bx = blockIdx.x, by = blockIdx.y;
    const int tid = threadIdx.x;
    const int lane = tid & 31, warp = tid >> 5;
    const int wm = warp % 2, wn = warp / 2;
    const int q = lane & 3, g = lane >> 2;

    float acc[16][4];
#pragma unroll
    for (int i = 0; i < 16; i++)
#pragma unroll
        for (int j = 0; j < 4; j++) acc[i][j] = 0.0f;

    gemm_mainloop3<2>(g_attn + (size_t)(by * 128) * HIDDEN,
                      g_wot + (size_t)(bx * 128) * HIDDEN, HIDDEN, acc);

#pragma unroll
    for (int mt = 0; mt < 4; mt++) {
        const int row = by * 128 + wm * 64 + mt * 16 + g;
#pragma unroll
        for (int nt = 0; nt < 4; nt++) {
            const int col = bx * 128 + wn * 32 + nt * 8 + (q << 1);
            *(float2*)(C + (size_t)row * HIDDEN + col) =
                make_float2(acc[mt * 4 + nt][0], acc[mt * 4 + nt][1]);
            *(float2*)(C + (size_t)(row + 8) * HIDDEN + col) =
                make_float2(acc[mt * 4 + nt][2], acc[mt * 4 + nt][3]);
        }
    }
}

// ---------------------------------------------------------------------------
// Flash attention: 64-row Q tiles, 4 warps, occ 3, cp.async K/V pipeline.
// P now stays in REGISTERS: C-layout -> A-layout via shfl.sync (no smem
// round-trip). K/V fragments via ldsm4 (V transposed [d][key]).
// ---------------------------------------------------------------------------
#define QSTR 68
#define FLASH_SMEM ((64 * QSTR * 3) * 4)

__global__ __launch_bounds__(128, 3)
void flash_tf32(const float* __restrict__ Q, const float* __restrict__ K,
                const float* __restrict__ V, float* __restrict__ O)
{
    extern __shared__ float sm[];
    float* Qs = sm;
    float* Ks = Qs + 64 * QSTR;
    float* Vs = Ks + 64 * QSTR;       // [64 d][QSTR] (transposed V tile)

    const int qb   = gridDim.x - 1 - blockIdx.x;   // heavy blocks first
    const int h    = blockIdx.y;
    const int b    = blockIdx.z;
    const int tid  = threadIdx.x;
    const int lane = tid & 31;
    const int warp = tid >> 5;
    const int q    = lane & 3;
    const int g    = lane >> 2;

    const float* Qg = Q + (((size_t)b * NH + h) * SEQ + qb * 64) * HD;
    const float* Kg = K + ((size_t)b * NKV + h / NREP) * SEQ * HD;
    const float* Vg = V + ((size_t)b * NKV + h / NREP) * HD * SEQ;  // [d][s]

    const uint32_t sKs = (uint32_t)__cvta_generic_to_shared(Ks);
    const uint32_t sVs = (uint32_t)__cvta_generic_to_shared(Vs);

    auto issue_k = [&](int kt) {
#pragma unroll
        for (int i = 0; i < 8; i++) {
            const int f = tid + 128 * i;
            const int r = f >> 4, c4 = (f & 15) << 2;
            const uint32_t d = sKs + (uint32_t)((r * QSTR + c4) * 4);
            const float* s = Kg + (size_t)kt * 64 * HD + f * 4;
            asm volatile("cp.async.cg.shared.global [%0], [%1], 16;" :: "r"(d), "l"(s));
        }
        asm volatile("cp.async.commit_group;");
    };
    auto issue_v = [&](int kt) {
#pragma unroll
        for (int i = 0; i < 8; i++) {
            const int f = tid + 128 * i;
            const int r = f >> 4, c4 = (f & 15) << 2;
            const uint32_t d = sVs + (uint32_t)((r * QSTR + c4) * 4);
            const float* s = Vg + (size_t)r * SEQ + kt * 64 + c4;
            asm volatile("cp.async.cg.shared.global [%0], [%1], 16;" :: "r"(d), "l"(s));
        }
        asm volatile("cp.async.commit_group;");
    };

    issue_k(0);
    issue_v(0);

#pragma unroll
    for (int i = 0; i < 8; i++) {
        const int f = tid + 128 * i;
        const int r = f >> 4, c4 = (f & 15) << 2;
        *(float4*)&Qs[r * QSTR + c4] = *(const float4*)&Qg[r * HD + c4];
    }
    __syncthreads();

    const int rA = warp * 16 + g;

    unsigned qf[8][4];
#pragma unroll
    for (int ks = 0; ks < 8; ks++) {
        const int k0 = ks * 8;
        qf[ks][0] = F2U(Qs[rA * QSTR + k0 + q]);
        qf[ks][1] = F2U(Qs[(rA + 8) * QSTR + k0 + q]);
        qf[ks][2] = F2U(Qs[rA * QSTR + k0 + 4 + q]);
        qf[ks][3] = F2U(Qs[(rA + 8) * QSTR + k0 + 4 + q]);
    }

    // ldmatrix bases for K / Vt B-fragments
    const int krow = (lane & 7) + ((lane >> 4) & 1) * 8;
    const int kcol = ((lane >> 3) & 1) * 4;
    const uint32_t kf4 = sKs + (uint32_t)((krow * QSTR + kcol) * 4);
    const uint32_t vf4 = sVs + (uint32_t)((krow * QSTR + kcol) * 4);

    // shfl source lanes for P C->A conversion
    const int ps0 = (lane & ~3) | (q >> 1);
    const int ps2 = ps0 + 2;
    const bool podd = (q & 1);

    float m_i[2], l_i[2], o_acc[8][4];
#pragma unroll
    for (int rh = 0; rh < 2; rh++) { m_i[rh] = -INFINITY; l_i[rh] = 0.0f; }
#pragma unroll
    for (int nt = 0; nt < 8; nt++)
#pragma unroll
        for (int j = 0; j < 4; j++) o_acc[nt][j] = 0.0f;

    for (int kt = 0; kt <= qb; kt++) {
        asm volatile("cp.async.wait_group 1;");
        __syncthreads();

        float s_acc[8][4];
#pragma unroll
        for (int nt = 0; nt < 8; nt++)
#pragma unroll
            for (int j = 0; j < 4; j++) s_acc[nt][j] = 0.0f;

#pragma unroll
        for (int ks = 0; ks < 8; ks++) {
#pragma unroll
            for (int ntp = 0; ntp < 4; ntp++) {
                unsigned b0, b1, b2, b3;
                ldsm4(b0, b1, b2, b3, kf4 + (uint32_t)((ntp * 16 * QSTR + ks * 8) * 4));
                mma8(s_acc[2 * ntp],     qf[ks][0], qf[ks][1], qf[ks][2], qf[ks][3], b0, b1);
                mma8(s_acc[2 * ntp + 1], qf[ks][0], qf[ks][1], qf[ks][2], qf[ks][3], b2, b3);
            }
        }

        const bool diag = (kt == qb);

#pragma unroll
        for (int rh = 0; rh < 2; rh++) {
            const int rg = qb * 64 + rA + rh * 8;
            float mx = -INFINITY;
#pragma unroll
            for (int nt = 0; nt < 8; nt++) {
#pragma unroll
                for (int j = 0; j < 2; j++) {
                    float sv = s_acc[nt][rh * 2 + j];
                    if (diag) {
                        int cg = kt * 64 + nt * 8 + (q << 1) + j;
                        if (cg > rg) sv = -INFINITY;
                    }
                    s_acc[nt][rh * 2 + j] = sv;
                    mx = fmaxf(mx, sv);
                }
            }
            mx = fmaxf(mx, __shfl_xor_sync(0xffffffffu, mx, 1));
            mx = fmaxf(mx, __shfl_xor_sync(0xffffffffu, mx, 2));

            const float mnew = fmaxf(m_i[rh], mx);
            const float sc = __expf(m_i[rh] - mnew);
            m_i[rh] = mnew;

            float rs = 0.0f;
#pragma unroll
            for (int nt = 0; nt < 8; nt++) {
#pragma unroll
                for (int j = 0; j < 2; j++) {
                    float p = __expf(s_acc[nt][rh * 2 + j] - mnew);
                    s_acc[nt][rh * 2 + j] = p;
                    rs += p;
                }
            }
            rs += __shfl_xor_sync(0xffffffffu, rs, 1);
            rs += __shfl_xor_sync(0xffffffffu, rs, 2);

            l_i[rh] = l_i[rh] * sc + rs;
#pragma unroll
            for (int nt = 0; nt < 8; nt++) {
                o_acc[nt][rh * 2]     *= sc;
                o_acc[nt][rh * 2 + 1] *= sc;
            }
        }

        asm volatile("cp.async.wait_group 0;");
        __syncthreads();
        if (kt < qb) issue_k(kt + 1);

        // O += P @ V: P A-fragments built from s_acc via shuffles.
        // A(g,q) needs P[rA][8ks+q], P[rA+8][8ks+q], P[rA][8ks+q+4], P[rA+8][8ks+q+4];
        // C-layout owner of col c is lane (g, c>>1), reg parity c&1.
#pragma unroll
        for (int ks = 0; ks < 8; ks++) {
            const float t00 = __shfl_sync(0xffffffffu, s_acc[ks][0], ps0);
            const float t01 = __shfl_sync(0xffffffffu, s_acc[ks][1], ps0);
            const float t10 = __shfl_sync(0xffffffffu, s_acc[ks][2], ps0);
            const float t11 = __shfl_sync(0xffffffffu, s_acc[ks][3], ps0);
            const float u00 = __shfl_sync(0xffffffffu, s_acc[ks][0], ps2);
            const float u01 = __shfl_sync(0xffffffffu, s_acc[ks][1], ps2);
            const float u10 = __shfl_sync(0xffffffffu, s_acc[ks][2], ps2);
            const float u11 = __shfl_sync(0xffffffffu, s_acc[ks][3], ps2);
            const unsigned a0 = F2U(tf32r(podd ? t01 : t00));
            const unsigned a1 = F2U(tf32r(podd ? t11 : t10));
            const unsigned a2 = F2U(tf32r(podd ? u01 : u00));
            const unsigned a3 = F2U(tf32r(podd ? u11 : u10));
#pragma unroll
            for (int ntp = 0; ntp < 4; ntp++) {
                unsigned b0, b1, b2, b3;
                ldsm4(b0, b1, b2, b3, vf4 + (uint32_t)((ntp * 16 * QSTR + ks * 8) * 4));
                mma8(o_acc[2 * ntp],     a0, a1, a2, a3, b0, b1);
                mma8(o_acc[2 * ntp + 1], a0, a1, a2, a3, b2, b3);
            }
        }
        __syncthreads();
        if (kt < qb) issue_v(kt + 1);
    }

    const float inv0 = 1.0f / l_i[0];
    const float inv1 = 1.0f / l_i[1];
#pragma unroll
    for (int nt = 0; nt < 8; nt++) {
        const int c = nt * 8 + (q << 1);
        const int r0 = qb * 64 + rA;
        float* p0 = O + ((size_t)b * SEQ + r0) * (NH * HD) + h * HD + c;
        p0[0] = tf32r(o_acc[nt][0] * inv0);
        p0[1] = tf32r(o_acc[nt][1] * inv0);
        float* p1 = O + ((size_t)b * SEQ + r0 + 8) * (NH * HD) + h * HD + c;
        p1[0] = tf32r(o_acc[nt][2] * inv1);
        p1[1] = tf32r(o_acc[nt][3] * inv1);
    }
}

// ---------------------------------------------------------------------------
// kernel_launch
// ---------------------------------------------------------------------------
extern "C" void kernel_launch(void* const* d_in, const int* in_sizes, int n_in,
                              void* d_out, int out_size)
{
    const float* hidden = (const float*)d_in[0];
    const float* wq = (const float*)d_in[1];
    const float* wk = (const float*)d_in[2];
    const float* wv = (const float*)d_in[3];
    const float* wo = (const float*)d_in[4];
    float* out = (float*)d_out;

    float *pq, *pk, *pv, *pattn, *pht;
    cudaGetSymbolAddress((void**)&pq, g_q);
    cudaGetSymbolAddress((void**)&pk, g_k);
    cudaGetSymbolAddress((void**)&pv, g_v);
    cudaGetSymbolAddress((void**)&pattn, g_attn);
    cudaGetSymbolAddress((void**)&pht, g_ht);

    const int M = BSZ * SEQ;   // 4096

    cudaFuncSetAttribute(qkv_gemm, cudaFuncAttributeMaxDynamicSharedMemorySize, GEMM_SMEM);
    cudaFuncSetAttribute(gemm_o, cudaFuncAttributeMaxDynamicSharedMemorySize, GEMM_SMEM);
    cudaFuncSetAttribute(flash_tf32, cudaFuncAttributeMaxDynamicSharedMemorySize, FLASH_SMEM);

    // 1) prologue: rope table, round hidden, transpose+round weights
    rope_fill<<<SEQ * 32 / 256, 256>>>();
    round_tf32<<<1184, 256>>>(hidden, pht, BSZ * SEQ * HIDDEN / 4);
    transpose_all<<<dim3(HIDDEN / 32, HIDDEN / 32, 4), dim3(32, 8)>>>(wq, wk, wv, wo);

    // 2) fused QKV projection + RoPE (24 N-tiles: 16 Q, 4 K, 4 V-transposed)
    qkv_gemm<<<dim3(24, M / 128), dim3(256), GEMM_SMEM>>>();

    // 3) flash attention (register-resident P via shuffles)
    flash_tf32<<<dim3(SEQ / 64, NH, BSZ), dim3(128), FLASH_SMEM>>>(pq, pk, pv, pattn);

    // 4) output projection
    gemm_o<<<dim3(HIDDEN / 128, M / 128), dim3(256), GEMM_SMEM>>>(out);
}